// round 3
// baseline (speedup 1.0000x reference)
#include <cuda_runtime.h>
#include <cuda_bf16.h>
#include <cstdint>

// Problem constants
#define BSZ      2
#define SEQLEN   2048
#define DIM      4096
#define NHEADS   32
#define NKV      8
#define HD       128
#define MROWS    (BSZ*SEQLEN)          // 4096

// Scratch (device globals: allocation-free rule)
__device__ float g_q[MROWS * DIM];           // 64 MB
__device__ float g_k[MROWS * NKV * HD];      // 16 MB
__device__ float g_v[MROWS * NKV * HD];      // 16 MB
__device__ float g_ctx[MROWS * DIM];         // 64 MB

// ---------------------------------------------------------------------------
// helpers
// ---------------------------------------------------------------------------
__device__ __forceinline__ float f2tf32(float x) {
    float y;
    asm("cvt.rna.tf32.f32 %0, %1;" : "=f"(y) : "f"(x));
    return y;
}

__device__ __forceinline__ void mma_tf32(float d[4], const float a[4],
                                         const float b[2], const float c[4]) {
    const uint32_t* A = reinterpret_cast<const uint32_t*>(a);
    const uint32_t* B = reinterpret_cast<const uint32_t*>(b);
    asm volatile(
        "mma.sync.aligned.m16n8k8.row.col.f32.tf32.tf32.f32 "
        "{%0,%1,%2,%3}, {%4,%5,%6,%7}, {%8,%9}, {%10,%11,%12,%13};\n"
        : "=f"(d[0]), "=f"(d[1]), "=f"(d[2]), "=f"(d[3])
        : "r"(A[0]), "r"(A[1]), "r"(A[2]), "r"(A[3]),
          "r"(B[0]), "r"(B[1]),
          "f"(c[0]), "f"(c[1]), "f"(c[2]), "f"(c[3]));
}

// ---------------------------------------------------------------------------
// Generic TF32 GEMM: C[M,N] = A[M,K] @ B[K,N], all row-major fp32.
// Block tile 128x128, K-tile 32, 256 threads (8 warps as 4x2, warp tile 32x64).
// ---------------------------------------------------------------------------
#define AS_STRIDE 36    // bank pattern for A-frag access: 4g+t4 (bijective)
#define BS_STRIDE 140   // bank pattern for B-frag access: 12t4+g (bijective)

__global__ __launch_bounds__(256) void gemm_tf32_kernel(
    const float* __restrict__ A, const float* __restrict__ B,
    float* __restrict__ C, int M, int N, int K, int lda, int ldb, int ldc)
{
    __shared__ float As[128 * AS_STRIDE];
    __shared__ float Bs[32 * BS_STRIDE];

    const int tid  = threadIdx.x;
    const int lane = tid & 31, warp = tid >> 5;
    const int g = lane >> 2, t4 = lane & 3;
    const int wm = warp >> 1, wn = warp & 1;
    const int bm = blockIdx.y * 128, bn = blockIdx.x * 128;

    float acc[2][8][4];
#pragma unroll
    for (int mi = 0; mi < 2; mi++)
#pragma unroll
        for (int ni = 0; ni < 8; ni++)
#pragma unroll
            for (int e = 0; e < 4; e++) acc[mi][ni][e] = 0.f;

    const int ar = tid >> 3, ac = (tid & 7) * 4;    // A loads: 32 rows/pass x 8 float4
    const int br = tid >> 5, bc = (tid & 31) * 4;   // B loads: 8 rows/pass x 32 float4

    for (int kt = 0; kt < K; kt += 32) {
#pragma unroll
        for (int p = 0; p < 4; p++) {
            int row = ar + p * 32;
            float4 v = *reinterpret_cast<const float4*>(
                &A[(size_t)(bm + row) * lda + kt + ac]);
            v.x = f2tf32(v.x); v.y = f2tf32(v.y); v.z = f2tf32(v.z); v.w = f2tf32(v.w);
            *reinterpret_cast<float4*>(&As[row * AS_STRIDE + ac]) = v;
        }
#pragma unroll
        for (int p = 0; p < 4; p++) {
            int row = br + p * 8;
            float4 v = *reinterpret_cast<const float4*>(
                &B[(size_t)(kt + row) * ldb + bn + bc]);
            v.x = f2tf32(v.x); v.y = f2tf32(v.y); v.z = f2tf32(v.z); v.w = f2tf32(v.w);
            *reinterpret_cast<float4*>(&Bs[row * BS_STRIDE + bc]) = v;
        }
        __syncthreads();

#pragma unroll
        for (int ks = 0; ks < 4; ks++) {
            float a[2][4], b[8][2];
#pragma unroll
            for (int mi = 0; mi < 2; mi++) {
                int r0 = wm * 32 + mi * 16 + g;
                a[mi][0] = As[r0 * AS_STRIDE + ks * 8 + t4];
                a[mi][1] = As[(r0 + 8) * AS_STRIDE + ks * 8 + t4];
                a[mi][2] = As[r0 * AS_STRIDE + ks * 8 + t4 + 4];
                a[mi][3] = As[(r0 + 8) * AS_STRIDE + ks * 8 + t4 + 4];
            }
#pragma unroll
            for (int ni = 0; ni < 8; ni++) {
                int cb = wn * 64 + ni * 8 + g;
                b[ni][0] = Bs[(ks * 8 + t4) * BS_STRIDE + cb];
                b[ni][1] = Bs[(ks * 8 + t4 + 4) * BS_STRIDE + cb];
            }
#pragma unroll
            for (int mi = 0; mi < 2; mi++)
#pragma unroll
                for (int ni = 0; ni < 8; ni++)
                    mma_tf32(acc[mi][ni], a[mi], b[ni], acc[mi][ni]);
        }
        __syncthreads();
    }

#pragma unroll
    for (int mi = 0; mi < 2; mi++)
#pragma unroll
        for (int ni = 0; ni < 8; ni++) {
            int r0 = bm + wm * 32 + mi * 16 + g;
            int cc = bn + wn * 64 + ni * 8 + t4 * 2;
            *reinterpret_cast<float2*>(&C[(size_t)r0 * ldc + cc]) =
                make_float2(acc[mi][ni][0], acc[mi][ni][1]);
            *reinterpret_cast<float2*>(&C[(size_t)(r0 + 8) * ldc + cc]) =
                make_float2(acc[mi][ni][2], acc[mi][ni][3]);
        }
}

// ---------------------------------------------------------------------------
// RoPE (interleaved even/odd pairs), in-place on [4096, nheads*128]
// ---------------------------------------------------------------------------
__global__ void rope_kernel(float* __restrict__ t, const float* __restrict__ fc,
                            const float* __restrict__ fs, int nheads)
{
    int idx = blockIdx.x * blockDim.x + threadIdx.x;  // one (row,head,freq) pair
    int fi = idx & 63;
    int hp = idx >> 6;
    int head = hp % nheads;
    int row = hp / nheads;
    int s = row & (SEQLEN - 1);
    float c = fc[s * 64 + fi], sn = fs[s * 64 + fi];
    float2* p = reinterpret_cast<float2*>(
        &t[(size_t)row * (nheads * HD) + head * HD + fi * 2]);
    float2 v = *p;
    *p = make_float2(v.x * c - v.y * sn, v.x * sn + v.y * c);
}

// ---------------------------------------------------------------------------
// Flash attention (causal, GQA). One CTA = 64 query rows of one (b,h).
// 4 warps, each owns 16 query rows. TF32 mma for QK^T and PV.
// ---------------------------------------------------------------------------
#define AT_STRIDE 140   // 140 mod 32 = 12: both frag access patterns bijective
#define ATTN_SMEM (4 * 64 * AT_STRIDE * 4)   // Qs,Ks,Vs,Ps = 143360 B

__global__ __launch_bounds__(128) void attn_kernel(
    const float* __restrict__ Q, const float* __restrict__ Kg,
    const float* __restrict__ Vg, float* __restrict__ ctx)
{
    extern __shared__ float sm[];
    float* Qs = sm;
    float* Ks = sm + 64 * AT_STRIDE;
    float* Vs = sm + 2 * 64 * AT_STRIDE;
    float* Ps = sm + 3 * 64 * AT_STRIDE;

    const int qt = blockIdx.x, h = blockIdx.y, b = blockIdx.z;
    const int hkv = h >> 2;
    const int tid = threadIdx.x, lane = tid & 31, warp = tid >> 5;
    const int g = lane >> 2, t4 = lane & 3;

    const int lr = tid >> 5;          // 0..3
    const int lc = (tid & 31) * 4;    // 0..124

    // Load Q tile (64 x 128), converted to tf32
#pragma unroll
    for (int p = 0; p < 16; p++) {
        int r = lr + p * 4;
        int gr = b * SEQLEN + qt * 64 + r;
        float4 v = *reinterpret_cast<const float4*>(
            &Q[(size_t)gr * DIM + h * HD + lc]);
        v.x = f2tf32(v.x); v.y = f2tf32(v.y); v.z = f2tf32(v.z); v.w = f2tf32(v.w);
        *reinterpret_cast<float4*>(&Qs[r * AT_STRIDE + lc]) = v;
    }

    float m_s[2] = {-1e30f, -1e30f};
    float l_s[2] = {0.f, 0.f};
    float o[16][4];
#pragma unroll
    for (int di = 0; di < 16; di++)
#pragma unroll
        for (int e = 0; e < 4; e++) o[di][e] = 0.f;

    const float scale = 0.08838834764831845f;  // 1/sqrt(128)

    for (int j = 0; j <= qt; j++) {
        __syncthreads();
#pragma unroll
        for (int p = 0; p < 16; p++) {
            int r = lr + p * 4;
            int gr = b * SEQLEN + j * 64 + r;
            float4 kv = *reinterpret_cast<const float4*>(
                &Kg[(size_t)gr * (NKV * HD) + hkv * HD + lc]);
            float4 vv = *reinterpret_cast<const float4*>(
                &Vg[(size_t)gr * (NKV * HD) + hkv * HD + lc]);
            kv.x = f2tf32(kv.x); kv.y = f2tf32(kv.y); kv.z = f2tf32(kv.z); kv.w = f2tf32(kv.w);
            vv.x = f2tf32(vv.x); vv.y = f2tf32(vv.y); vv.z = f2tf32(vv.z); vv.w = f2tf32(vv.w);
            *reinterpret_cast<float4*>(&Ks[r * AT_STRIDE + lc]) = kv;
            *reinterpret_cast<float4*>(&Vs[r * AT_STRIDE + lc]) = vv;
        }
        __syncthreads();

        // S = Q @ K^T  (16 rows per warp x 64 keys), k-dim 128
        float s[8][4];
#pragma unroll
        for (int ni = 0; ni < 8; ni++)
#pragma unroll
            for (int e = 0; e < 4; e++) s[ni][e] = 0.f;

#pragma unroll
        for (int ks = 0; ks < 16; ks++) {
            float a[4];
            int r0 = warp * 16 + g;
            a[0] = Qs[r0 * AT_STRIDE + ks * 8 + t4];
            a[1] = Qs[(r0 + 8) * AT_STRIDE + ks * 8 + t4];
            a[2] = Qs[r0 * AT_STRIDE + ks * 8 + t4 + 4];
            a[3] = Qs[(r0 + 8) * AT_STRIDE + ks * 8 + t4 + 4];
#pragma unroll
            for (int ni = 0; ni < 8; ni++) {
                float bf[2];
                bf[0] = Ks[(ni * 8 + g) * AT_STRIDE + ks * 8 + t4];
                bf[1] = Ks[(ni * 8 + g) * AT_STRIDE + ks * 8 + t4 + 4];
                mma_tf32(s[ni], a, bf, s[ni]);
            }
        }

        // scale + causal mask (diagonal tile only)
#pragma unroll
        for (int ni = 0; ni < 8; ni++)
#pragma unroll
            for (int e = 0; e < 4; e++) s[ni][e] *= scale;
        if (j == qt) {
#pragma unroll
            for (int ni = 0; ni < 8; ni++)
#pragma unroll
                for (int e = 0; e < 4; e++) {
                    int qr = warp * 16 + g + (e >> 1) * 8;
                    int kc = ni * 8 + t4 * 2 + (e & 1);
                    if (kc > qr) s[ni][e] = -1e30f;
                }
        }

        // online softmax per row (each thread: rows g and g+8 of its warp tile)
#pragma unroll
        for (int rr = 0; rr < 2; rr++) {
            float mx = -1e30f;
#pragma unroll
            for (int ni = 0; ni < 8; ni++)
                mx = fmaxf(mx, fmaxf(s[ni][rr * 2], s[ni][rr * 2 + 1]));
            mx = fmaxf(mx, __shfl_xor_sync(0xffffffffu, mx, 1));
            mx = fmaxf(mx, __shfl_xor_sync(0xffffffffu, mx, 2));
            float nm = fmaxf(m_s[rr], mx);
            float alpha = __expf(m_s[rr] - nm);
            m_s[rr] = nm;
            float rsum = 0.f;
#pragma unroll
            for (int ni = 0; ni < 8; ni++) {
#pragma unroll
                for (int cc = 0; cc < 2; cc++) {
                    float pv = __expf(s[ni][rr * 2 + cc] - nm);
                    s[ni][rr * 2 + cc] = pv;
                    rsum += pv;
                }
            }
            rsum += __shfl_xor_sync(0xffffffffu, rsum, 1);
            rsum += __shfl_xor_sync(0xffffffffu, rsum, 2);
            l_s[rr] = l_s[rr] * alpha + rsum;
#pragma unroll
            for (int di = 0; di < 16; di++) {
                o[di][rr * 2] *= alpha;
                o[di][rr * 2 + 1] *= alpha;
            }
        }

        __syncwarp();
        // stage P in smem (tf32), each warp owns its 16 rows
#pragma unroll
        for (int ni = 0; ni < 8; ni++)
#pragma unroll
            for (int e = 0; e < 4; e++) {
                int pr = warp * 16 + g + (e >> 1) * 8;
                int pc = ni * 8 + t4 * 2 + (e & 1);
                Ps[pr * AT_STRIDE + pc] = f2tf32(s[ni][e]);
            }
        __syncwarp();

        // O += P @ V   (k-dim = 64 keys, n-dim = 128 head dims)
#pragma unroll
        for (int ks = 0; ks < 8; ks++) {
            float a[4];
            int r0 = warp * 16 + g;
            a[0] = Ps[r0 * AT_STRIDE + ks * 8 + t4];
            a[1] = Ps[(r0 + 8) * AT_STRIDE + ks * 8 + t4];
            a[2] = Ps[r0 * AT_STRIDE + ks * 8 + t4 + 4];
            a[3] = Ps[(r0 + 8) * AT_STRIDE + ks * 8 + t4 + 4];
#pragma unroll
            for (int di = 0; di < 16; di++) {
                float bf[2];
                bf[0] = Vs[(ks * 8 + t4) * AT_STRIDE + di * 8 + g];
                bf[1] = Vs[(ks * 8 + t4 + 4) * AT_STRIDE + di * 8 + g];
                mma_tf32(o[di], a, bf, o[di]);
            }
        }
    }

    // normalize + write ctx in [row][h*128+d] layout
#pragma unroll
    for (int rr = 0; rr < 2; rr++) {
        float inv = 1.0f / l_s[rr];
        int gr = b * SEQLEN + qt * 64 + warp * 16 + g + rr * 8;
#pragma unroll
        for (int di = 0; di < 16; di++) {
            float2 v = make_float2(o[di][rr * 2] * inv, o[di][rr * 2 + 1] * inv);
            *reinterpret_cast<float2*>(
                &ctx[(size_t)gr * DIM + h * HD + di * 8 + t4 * 2]) = v;
        }
    }
}

// ---------------------------------------------------------------------------
// launch
// ---------------------------------------------------------------------------
extern "C" void kernel_launch(void* const* d_in, const int* in_sizes, int n_in,
                              void* d_out, int out_size)
{
    const float* x  = (const float*)d_in[0];
    const float* wq = (const float*)d_in[1];
    const float* wk = (const float*)d_in[2];
    const float* wv = (const float*)d_in[3];
    const float* wo = (const float*)d_in[4];
    const float* fc = (const float*)d_in[5];
    const float* fs = (const float*)d_in[6];
    // d_in[7] = mask (causal, applied analytically), d_in[8] = start_pos (0)
    float* out = (float*)d_out;

    float *q, *k, *v, *ctx;
    cudaGetSymbolAddress((void**)&q,   g_q);
    cudaGetSymbolAddress((void**)&k,   g_k);
    cudaGetSymbolAddress((void**)&v,   g_v);
    cudaGetSymbolAddress((void**)&ctx, g_ctx);

    cudaFuncSetAttribute(attn_kernel,
                         cudaFuncAttributeMaxDynamicSharedMemorySize, ATTN_SMEM);

    // QKV projections
    gemm_tf32_kernel<<<dim3(32, 32), 256>>>(x, wq, q, MROWS, DIM, DIM, DIM, DIM, DIM);
    gemm_tf32_kernel<<<dim3(8, 32), 256>>>(x, wk, k, MROWS, NKV * HD, DIM, DIM, NKV * HD, NKV * HD);
    gemm_tf32_kernel<<<dim3(8, 32), 256>>>(x, wv, v, MROWS, NKV * HD, DIM, DIM, NKV * HD, NKV * HD);

    // RoPE on Q and K
    rope_kernel<<<(MROWS * NHEADS * 64) / 256, 256>>>(q, fc, fs, NHEADS);
    rope_kernel<<<(MROWS * NKV * 64) / 256, 256>>>(k, fc, fs, NKV);

    // Causal flash attention
    attn_kernel<<<dim3(SEQLEN / 64, NHEADS, BSZ), 128, ATTN_SMEM>>>(q, k, v, ctx);

    // Output projection
    gemm_tf32_kernel<<<dim3(32, 32), 256>>>(ctx, wo, out, MROWS, DIM, DIM, DIM, DIM, DIM);
}

// round 4
// speedup vs baseline: 1.3830x; 1.3830x over previous
#include <cuda_runtime.h>
#include <cuda_bf16.h>
#include <cstdint>

// Problem constants
#define BSZ      2
#define SEQLEN   2048
#define DIM      4096
#define NHEADS   32
#define NKV      8
#define HD       128
#define MROWS    (BSZ*SEQLEN)          // 4096
#define KVDIM    (NKV*HD)              // 1024

// Scratch (device globals: allocation-free rule)
__device__ float g_q[MROWS * DIM];
__device__ float g_k[MROWS * KVDIM];
__device__ float g_v[MROWS * KVDIM];
__device__ float g_ctx[MROWS * DIM];
// tf32-pre-rounded copies (enable cp.async without per-element cvt in hot loops)
__device__ float g_xt[MROWS * DIM];
__device__ float g_wqt[DIM * DIM];
__device__ float g_wkt[DIM * KVDIM];
__device__ float g_wvt[DIM * KVDIM];
__device__ float g_wot[DIM * DIM];

// ---------------------------------------------------------------------------
// helpers
// ---------------------------------------------------------------------------
__device__ __forceinline__ float f2tf32(float x) {
    float y;
    asm("cvt.rna.tf32.f32 %0, %1;" : "=f"(y) : "f"(x));
    return y;
}

__device__ __forceinline__ void mma_tf32(float d[4], const float a[4],
                                         const float b[2], const float c[4]) {
    const uint32_t* A = reinterpret_cast<const uint32_t*>(a);
    const uint32_t* B = reinterpret_cast<const uint32_t*>(b);
    asm volatile(
        "mma.sync.aligned.m16n8k8.row.col.f32.tf32.tf32.f32 "
        "{%0,%1,%2,%3}, {%4,%5,%6,%7}, {%8,%9}, {%10,%11,%12,%13};\n"
        : "=f"(d[0]), "=f"(d[1]), "=f"(d[2]), "=f"(d[3])
        : "r"(A[0]), "r"(A[1]), "r"(A[2]), "r"(A[3]),
          "r"(B[0]), "r"(B[1]),
          "f"(c[0]), "f"(c[1]), "f"(c[2]), "f"(c[3]));
}

__device__ __forceinline__ void cp_async16(void* smem, const void* gmem) {
    uint32_t s = (uint32_t)__cvta_generic_to_shared(smem);
    asm volatile("cp.async.cg.shared.global [%0], [%1], 16;\n" :: "r"(s), "l"(gmem));
}
__device__ __forceinline__ void cp_commit() {
    asm volatile("cp.async.commit_group;\n" ::: "memory");
}
template<int N> __device__ __forceinline__ void cp_wait() {
    asm volatile("cp.async.wait_group %0;\n" :: "n"(N) : "memory");
}

// ---------------------------------------------------------------------------
// Elementwise tf32 pre-rounding (vectorized)
// ---------------------------------------------------------------------------
__global__ void cvt_tf32_kernel(const float4* __restrict__ in,
                                float4* __restrict__ out, int n4)
{
    int i = blockIdx.x * blockDim.x + threadIdx.x;
    if (i < n4) {
        float4 v = in[i];
        v.x = f2tf32(v.x); v.y = f2tf32(v.y); v.z = f2tf32(v.z); v.w = f2tf32(v.w);
        out[i] = v;
    }
}

// ---------------------------------------------------------------------------
// TF32 GEMM v2: C[M,N] = A[M,K] @ B[K,N], row-major fp32 (A/B pre-rounded).
// Block 128x128, BK=32, 256 threads (8 warps 4x2, warp tile 32x64),
// 3-stage cp.async pipeline.
// ---------------------------------------------------------------------------
#define BM 128
#define BN 128
#define BK 32
#define ASTR 36      // A smem row stride (floats): frag bank pattern 4g+t4 bijective
#define BSTR 132     // B smem row stride: frag bank pattern 4*t4+g bijective
#define A_ST (BM*ASTR)            // 4608 floats
#define B_ST (BK*BSTR)            // 4224 floats
#define STG_FLT (A_ST + B_ST)     // 8832 floats
#define NSTG 3
#define GEMM_SMEM (NSTG*STG_FLT*4) // 105984 B -> 2 CTAs/SM

__global__ __launch_bounds__(256, 2) void gemm_tf32_kernel(
    const float* __restrict__ A, const float* __restrict__ B,
    float* __restrict__ C, int M, int N, int K,
    int lda, int ldb, int ldc, int roundOut)
{
    extern __shared__ float sm[];

    const int tid  = threadIdx.x;
    const int lane = tid & 31, warp = tid >> 5;
    const int g = lane >> 2, t4 = lane & 3;
    const int wm = warp >> 1, wn = warp & 1;
    const int bm = blockIdx.y * BM, bn = blockIdx.x * BN;

    const int ar = tid >> 3, ac = (tid & 7) * 4;    // A: 32 rows/pass x 8 f4
    const int br = tid >> 5, bc = (tid & 31) * 4;   // B: 8 rows/pass x 32 f4
    const int ktiles = K / BK;

    float acc[2][8][4];
#pragma unroll
    for (int mi = 0; mi < 2; mi++)
#pragma unroll
        for (int ni = 0; ni < 8; ni++)
#pragma unroll
            for (int e = 0; e < 4; e++) acc[mi][ni][e] = 0.f;

    auto issue = [&](int stg, int t) {
        if (t < ktiles) {
            float* As = sm + stg * STG_FLT;
            float* Bs = As + A_ST;
            const int kt = t * BK;
#pragma unroll
            for (int p = 0; p < 4; p++) {
                int row = ar + p * 32;
                cp_async16(&As[row * ASTR + ac],
                           &A[(size_t)(bm + row) * lda + kt + ac]);
            }
#pragma unroll
            for (int p = 0; p < 4; p++) {
                int row = br + p * 8;
                cp_async16(&Bs[row * BSTR + bc],
                           &B[(size_t)(kt + row) * ldb + bn + bc]);
            }
        }
        cp_commit();   // commit even when empty: keeps group count uniform
    };

    issue(0, 0);
    issue(1, 1);

    for (int t = 0; t < ktiles; t++) {
        cp_wait<1>();          // group t complete (t+1 may stay in flight)
        __syncthreads();       // also fences: everyone done computing tile t-1
        issue((t + 2) % NSTG, t + 2);   // overwrites stage of tile t-1 (safe)

        const float* As = sm + (t % NSTG) * STG_FLT;
        const float* Bs = As + A_ST;

#pragma unroll
        for (int ks = 0; ks < 4; ks++) {
            float a[2][4], b[8][2];
#pragma unroll
            for (int mi = 0; mi < 2; mi++) {
                int r0 = wm * 32 + mi * 16 + g;
                a[mi][0] = As[r0 * ASTR + ks * 8 + t4];
                a[mi][1] = As[(r0 + 8) * ASTR + ks * 8 + t4];
                a[mi][2] = As[r0 * ASTR + ks * 8 + t4 + 4];
                a[mi][3] = As[(r0 + 8) * ASTR + ks * 8 + t4 + 4];
            }
#pragma unroll
            for (int ni = 0; ni < 8; ni++) {
                int cb = wn * 64 + ni * 8 + g;
                b[ni][0] = Bs[(ks * 8 + t4) * BSTR + cb];
                b[ni][1] = Bs[(ks * 8 + t4 + 4) * BSTR + cb];
            }
#pragma unroll
            for (int mi = 0; mi < 2; mi++)
#pragma unroll
                for (int ni = 0; ni < 8; ni++)
                    mma_tf32(acc[mi][ni], a[mi], b[ni], acc[mi][ni]);
        }
        // no trailing barrier needed: next iteration's wait+sync protects reuse
    }

#pragma unroll
    for (int mi = 0; mi < 2; mi++)
#pragma unroll
        for (int ni = 0; ni < 8; ni++) {
            float v0 = acc[mi][ni][0], v1 = acc[mi][ni][1];
            float v2 = acc[mi][ni][2], v3 = acc[mi][ni][3];
            if (roundOut) {
                v0 = f2tf32(v0); v1 = f2tf32(v1);
                v2 = f2tf32(v2); v3 = f2tf32(v3);
            }
            int r0 = bm + wm * 32 + mi * 16 + g;
            int cc = bn + wn * 64 + ni * 8 + t4 * 2;
            *reinterpret_cast<float2*>(&C[(size_t)r0 * ldc + cc]) = make_float2(v0, v1);
            *reinterpret_cast<float2*>(&C[(size_t)(r0 + 8) * ldc + cc]) = make_float2(v2, v3);
        }
}

// ---------------------------------------------------------------------------
// RoPE (interleaved pairs), in-place; output tf32-rounded for attention mma.
// ---------------------------------------------------------------------------
__global__ void rope_kernel(float* __restrict__ t, const float* __restrict__ fc,
                            const float* __restrict__ fs, int nheads)
{
    int idx = blockIdx.x * blockDim.x + threadIdx.x;
    int fi = idx & 63;
    int hp = idx >> 6;
    int head = hp % nheads;
    int row = hp / nheads;
    int s = row & (SEQLEN - 1);
    float c = fc[s * 64 + fi], sn = fs[s * 64 + fi];
    float2* p = reinterpret_cast<float2*>(
        &t[(size_t)row * (nheads * HD) + head * HD + fi * 2]);
    float2 v = *p;
    *p = make_float2(f2tf32(v.x * c - v.y * sn), f2tf32(v.x * sn + v.y * c));
}

// ---------------------------------------------------------------------------
// Flash attention (causal, GQA). One CTA = 64 query rows of one (b,h).
// 4 warps x 16 q-rows. K/V double-buffered via cp.async. Inputs pre-rounded.
// ---------------------------------------------------------------------------
#define ATS 140                    // 140 mod 32 = 12: frag patterns bijective
#define AT_FL (64 * ATS)           // 8960 floats per tile array
#define ATTN_SMEM (6 * AT_FL * 4)  // Q + 2K + 2V + P = 215040 B

__global__ __launch_bounds__(128) void attn_kernel(
    const float* __restrict__ Q, const float* __restrict__ Kg,
    const float* __restrict__ Vg, float* __restrict__ ctx)
{
    extern __shared__ float sm[];
    float* Qs  = sm;
    float* Ksb[2] = { sm + AT_FL,     sm + 2 * AT_FL };
    float* Vsb[2] = { sm + 3 * AT_FL, sm + 4 * AT_FL };
    float* Ps  = sm + 5 * AT_FL;

    const int qt = blockIdx.x, h = blockIdx.y, b = blockIdx.z;
    const int hkv = h >> 2;
    const int tid = threadIdx.x, lane = tid & 31, warp = tid >> 5;
    const int g = lane >> 2, t4 = lane & 3;

    const int lr = tid >> 5;          // 0..3
    const int lc = (tid & 31) * 4;    // 0..124

    // Load Q tile (64 x 128) — already tf32-rounded by rope
#pragma unroll
    for (int p = 0; p < 16; p++) {
        int r = lr + p * 4;
        int gr = b * SEQLEN + qt * 64 + r;
        *reinterpret_cast<float4*>(&Qs[r * ATS + lc]) =
            *reinterpret_cast<const float4*>(&Q[(size_t)gr * DIM + h * HD + lc]);
    }

    auto issue_kv = [&](int buf, int j) {
        float* Ks = Ksb[buf];
        float* Vs = Vsb[buf];
#pragma unroll
        for (int p = 0; p < 16; p++) {
            int r = lr + p * 4;
            int gr = b * SEQLEN + j * 64 + r;
            cp_async16(&Ks[r * ATS + lc], &Kg[(size_t)gr * KVDIM + hkv * HD + lc]);
            cp_async16(&Vs[r * ATS + lc], &Vg[(size_t)gr * KVDIM + hkv * HD + lc]);
        }
        cp_commit();
    };

    float m_s[2] = {-1e30f, -1e30f};
    float l_s[2] = {0.f, 0.f};
    float o[16][4];
#pragma unroll
    for (int di = 0; di < 16; di++)
#pragma unroll
        for (int e = 0; e < 4; e++) o[di][e] = 0.f;

    const float scale = 0.08838834764831845f;  // 1/sqrt(128)

    issue_kv(0, 0);

    for (int j = 0; j <= qt; j++) {
        cp_wait<0>();
        __syncthreads();            // data visible; compute of j-1 done everywhere
        if (j + 1 <= qt) issue_kv((j + 1) & 1, j + 1);  // overlaps compute of j

        const float* Ks = Ksb[j & 1];
        const float* Vs = Vsb[j & 1];

        // S = Q @ K^T (16 rows/warp x 64 keys), k-dim 128
        float s[8][4];
#pragma unroll
        for (int ni = 0; ni < 8; ni++)
#pragma unroll
            for (int e = 0; e < 4; e++) s[ni][e] = 0.f;

#pragma unroll
        for (int ks = 0; ks < 16; ks++) {
            float a[4];
            int r0 = warp * 16 + g;
            a[0] = Qs[r0 * ATS + ks * 8 + t4];
            a[1] = Qs[(r0 + 8) * ATS + ks * 8 + t4];
            a[2] = Qs[r0 * ATS + ks * 8 + t4 + 4];
            a[3] = Qs[(r0 + 8) * ATS + ks * 8 + t4 + 4];
#pragma unroll
            for (int ni = 0; ni < 8; ni++) {
                float bf[2];
                bf[0] = Ks[(ni * 8 + g) * ATS + ks * 8 + t4];
                bf[1] = Ks[(ni * 8 + g) * ATS + ks * 8 + t4 + 4];
                mma_tf32(s[ni], a, bf, s[ni]);
            }
        }

        // scale + causal mask (diagonal tile only)
#pragma unroll
        for (int ni = 0; ni < 8; ni++)
#pragma unroll
            for (int e = 0; e < 4; e++) s[ni][e] *= scale;
        if (j == qt) {
#pragma unroll
            for (int ni = 0; ni < 8; ni++)
#pragma unroll
                for (int e = 0; e < 4; e++) {
                    int qr = warp * 16 + g + (e >> 1) * 8;
                    int kc = ni * 8 + t4 * 2 + (e & 1);
                    if (kc > qr) s[ni][e] = -1e30f;
                }
        }

        // online softmax per row (thread rows g, g+8 of warp tile)
#pragma unroll
        for (int rr = 0; rr < 2; rr++) {
            float mx = -1e30f;
#pragma unroll
            for (int ni = 0; ni < 8; ni++)
                mx = fmaxf(mx, fmaxf(s[ni][rr * 2], s[ni][rr * 2 + 1]));
            mx = fmaxf(mx, __shfl_xor_sync(0xffffffffu, mx, 1));
            mx = fmaxf(mx, __shfl_xor_sync(0xffffffffu, mx, 2));
            float nm = fmaxf(m_s[rr], mx);
            float alpha = __expf(m_s[rr] - nm);
            m_s[rr] = nm;
            float rsum = 0.f;
#pragma unroll
            for (int ni = 0; ni < 8; ni++) {
#pragma unroll
                for (int cc = 0; cc < 2; cc++) {
                    float pv = __expf(s[ni][rr * 2 + cc] - nm);
                    s[ni][rr * 2 + cc] = pv;
                    rsum += pv;
                }
            }
            rsum += __shfl_xor_sync(0xffffffffu, rsum, 1);
            rsum += __shfl_xor_sync(0xffffffffu, rsum, 2);
            l_s[rr] = l_s[rr] * alpha + rsum;
#pragma unroll
            for (int di = 0; di < 16; di++) {
                o[di][rr * 2] *= alpha;
                o[di][rr * 2 + 1] *= alpha;
            }
        }

        __syncwarp();
        // stage P (tf32) in smem, warp-private rows
#pragma unroll
        for (int ni = 0; ni < 8; ni++)
#pragma unroll
            for (int e = 0; e < 4; e++) {
                int pr = warp * 16 + g + (e >> 1) * 8;
                int pc = ni * 8 + t4 * 2 + (e & 1);
                Ps[pr * ATS + pc] = f2tf32(s[ni][e]);
            }
        __syncwarp();

        // O += P @ V
#pragma unroll
        for (int ks = 0; ks < 8; ks++) {
            float a[4];
            int r0 = warp * 16 + g;
            a[0] = Ps[r0 * ATS + ks * 8 + t4];
            a[1] = Ps[(r0 + 8) * ATS + ks * 8 + t4];
            a[2] = Ps[r0 * ATS + ks * 8 + t4 + 4];
            a[3] = Ps[(r0 + 8) * ATS + ks * 8 + t4 + 4];
#pragma unroll
            for (int di = 0; di < 16; di++) {
                float bf[2];
                bf[0] = Vs[(ks * 8 + t4) * ATS + di * 8 + g];
                bf[1] = Vs[(ks * 8 + t4 + 4) * ATS + di * 8 + g];
                mma_tf32(o[di], a, bf, o[di]);
            }
        }
    }

    // normalize + tf32-round + write ctx [row][h*128+d]
#pragma unroll
    for (int rr = 0; rr < 2; rr++) {
        float inv = 1.0f / l_s[rr];
        int gr = b * SEQLEN + qt * 64 + warp * 16 + g + rr * 8;
#pragma unroll
        for (int di = 0; di < 16; di++) {
            float2 v = make_float2(f2tf32(o[di][rr * 2] * inv),
                                   f2tf32(o[di][rr * 2 + 1] * inv));
            *reinterpret_cast<float2*>(
                &ctx[(size_t)gr * DIM + h * HD + di * 8 + t4 * 2]) = v;
        }
    }
}

// ---------------------------------------------------------------------------
// launch
// ---------------------------------------------------------------------------
extern "C" void kernel_launch(void* const* d_in, const int* in_sizes, int n_in,
                              void* d_out, int out_size)
{
    const float* x  = (const float*)d_in[0];
    const float* wq = (const float*)d_in[1];
    const float* wk = (const float*)d_in[2];
    const float* wv = (const float*)d_in[3];
    const float* wo = (const float*)d_in[4];
    const float* fc = (const float*)d_in[5];
    const float* fs = (const float*)d_in[6];
    // d_in[7] = mask (causal, applied analytically), d_in[8] = start_pos (0)
    float* out = (float*)d_out;

    float *q, *k, *v, *ctx, *xt, *wqt, *wkt, *wvt, *wot;
    cudaGetSymbolAddress((void**)&q,   g_q);
    cudaGetSymbolAddress((void**)&k,   g_k);
    cudaGetSymbolAddress((void**)&v,   g_v);
    cudaGetSymbolAddress((void**)&ctx, g_ctx);
    cudaGetSymbolAddress((void**)&xt,  g_xt);
    cudaGetSymbolAddress((void**)&wqt, g_wqt);
    cudaGetSymbolAddress((void**)&wkt, g_wkt);
    cudaGetSymbolAddress((void**)&wvt, g_wvt);
    cudaGetSymbolAddress((void**)&wot, g_wot);

    cudaFuncSetAttribute(gemm_tf32_kernel,
                         cudaFuncAttributeMaxDynamicSharedMemorySize, GEMM_SMEM);
    cudaFuncSetAttribute(attn_kernel,
                         cudaFuncAttributeMaxDynamicSharedMemorySize, ATTN_SMEM);

    // tf32 pre-rounding (hoists cvt out of GEMM hot loops; enables cp.async)
    const int C256 = 256;
    int n4_big = MROWS * DIM / 4;         // 4194304
    int n4_w   = DIM * DIM / 4;           // 4194304
    int n4_kv  = DIM * KVDIM / 4;         // 1048576
    cvt_tf32_kernel<<<(n4_big + C256 - 1) / C256, C256>>>((const float4*)x,  (float4*)xt,  n4_big);
    cvt_tf32_kernel<<<(n4_w   + C256 - 1) / C256, C256>>>((const float4*)wq, (float4*)wqt, n4_w);
    cvt_tf32_kernel<<<(n4_kv  + C256 - 1) / C256, C256>>>((const float4*)wk, (float4*)wkt, n4_kv);
    cvt_tf32_kernel<<<(n4_kv  + C256 - 1) / C256, C256>>>((const float4*)wv, (float4*)wvt, n4_kv);
    cvt_tf32_kernel<<<(n4_w   + C256 - 1) / C256, C256>>>((const float4*)wo, (float4*)wot, n4_w);

    // QKV projections (V output rounded for attention mma)
    gemm_tf32_kernel<<<dim3(32, 32), 256, GEMM_SMEM>>>(xt, wqt, q, MROWS, DIM,   DIM, DIM, DIM,   DIM,   0);
    gemm_tf32_kernel<<<dim3(8,  32), 256, GEMM_SMEM>>>(xt, wkt, k, MROWS, KVDIM, DIM, DIM, KVDIM, KVDIM, 0);
    gemm_tf32_kernel<<<dim3(8,  32), 256, GEMM_SMEM>>>(xt, wvt, v, MROWS, KVDIM, DIM, DIM, KVDIM, KVDIM, 1);

    // RoPE on Q and K (outputs tf32-rounded)
    rope_kernel<<<(MROWS * NHEADS * 64) / 256, 256>>>(q, fc, fs, NHEADS);
    rope_kernel<<<(MROWS * NKV * 64) / 256, 256>>>(k, fc, fs, NKV);

    // Causal flash attention
    attn_kernel<<<dim3(SEQLEN / 64, NHEADS, BSZ), 128, ATTN_SMEM>>>(q, k, v, ctx);

    // Output projection
    gemm_tf32_kernel<<<dim3(32, 32), 256, GEMM_SMEM>>>(ctx, wot, out, MROWS, DIM, DIM, DIM, DIM, DIM, 0);
}

// round 6
// speedup vs baseline: 1.6559x; 1.1973x over previous
#include <cuda_runtime.h>
#include <cuda_bf16.h>
#include <cstdint>

// Problem constants
#define BSZ      2
#define SEQLEN   2048
#define DIM      4096
#define NHEADS   32
#define NKV      8
#define HD       128
#define MROWS    (BSZ*SEQLEN)          // 4096
#define KVDIM    (NKV*HD)              // 1024

// Scratch (device globals: allocation-free rule)
__device__ float g_q[MROWS * DIM];
__device__ float g_k[MROWS * KVDIM];
__device__ float g_v[MROWS * KVDIM];
__device__ float g_ctx[MROWS * DIM];
// tf32-pre-rounded A operand + transposed tf32 weights ([N,K] K-major)
__device__ float g_xt[MROWS * DIM];
__device__ float g_wqt[DIM * DIM];
__device__ float g_wkt[DIM * KVDIM];
__device__ float g_wvt[DIM * KVDIM];
__device__ float g_wot[DIM * DIM];

// ---------------------------------------------------------------------------
// helpers
// ---------------------------------------------------------------------------
__device__ __forceinline__ float f2tf32(float x) {
    float y;
    asm("cvt.rna.tf32.f32 %0, %1;" : "=f"(y) : "f"(x));
    return y;
}

__device__ __forceinline__ void mma_tf32(float d[4], const uint32_t a[4],
                                         const uint32_t b[2], const float c[4]) {
    asm volatile(
        "mma.sync.aligned.m16n8k8.row.col.f32.tf32.tf32.f32 "
        "{%0,%1,%2,%3}, {%4,%5,%6,%7}, {%8,%9}, {%10,%11,%12,%13};\n"
        : "=f"(d[0]), "=f"(d[1]), "=f"(d[2]), "=f"(d[3])
        : "r"(a[0]), "r"(a[1]), "r"(a[2]), "r"(a[3]),
          "r"(b[0]), "r"(b[1]),
          "f"(c[0]), "f"(c[1]), "f"(c[2]), "f"(c[3]));
}

__device__ __forceinline__ void mma_tf32f(float d[4], const float a[4],
                                          const float b[2], const float c[4]) {
    mma_tf32(d, reinterpret_cast<const uint32_t*>(a),
             reinterpret_cast<const uint32_t*>(b), c);
}

__device__ __forceinline__ void ldsm_x4(uint32_t d[4], uint32_t addr) {
    asm volatile(
        "ldmatrix.sync.aligned.m8n8.x4.shared.b16 {%0,%1,%2,%3}, [%4];"
        : "=r"(d[0]), "=r"(d[1]), "=r"(d[2]), "=r"(d[3]) : "r"(addr));
}

__device__ __forceinline__ void cp_async16(void* smem, const void* gmem) {
    uint32_t s = (uint32_t)__cvta_generic_to_shared(smem);
    asm volatile("cp.async.cg.shared.global [%0], [%1], 16;\n" :: "r"(s), "l"(gmem));
}
__device__ __forceinline__ void cp_commit() {
    asm volatile("cp.async.commit_group;\n" ::: "memory");
}
template<int N> __device__ __forceinline__ void cp_wait() {
    asm volatile("cp.async.wait_group %0;\n" :: "n"(N) : "memory");
}

// ---------------------------------------------------------------------------
// Elementwise tf32 pre-rounding (x)
// ---------------------------------------------------------------------------
__global__ void cvt_tf32_kernel(const float4* __restrict__ in,
                                float4* __restrict__ out, int n4)
{
    int i = blockIdx.x * blockDim.x + threadIdx.x;
    if (i < n4) {
        float4 v = in[i];
        v.x = f2tf32(v.x); v.y = f2tf32(v.y); v.z = f2tf32(v.z); v.w = f2tf32(v.w);
        out[i] = v;
    }
}

// ---------------------------------------------------------------------------
// Fused transpose + tf32 round: in[K,N] -> out[N,K]
// ---------------------------------------------------------------------------
__global__ void transpose_cvt_kernel(const float* __restrict__ in,
                                     float* __restrict__ out, int K, int N)
{
    __shared__ float t[32][33];
    int k0 = blockIdx.y * 32, n0 = blockIdx.x * 32;
    int tx = threadIdx.x, ty = threadIdx.y;
#pragma unroll
    for (int i = 0; i < 4; i++)
        t[ty + 8 * i][tx] = in[(size_t)(k0 + ty + 8 * i) * N + n0 + tx];
    __syncthreads();
#pragma unroll
    for (int i = 0; i < 4; i++)
        out[(size_t)(n0 + ty + 8 * i) * K + k0 + tx] = f2tf32(t[tx][ty + 8 * i]);
}

// ---------------------------------------------------------------------------
// TF32 GEMM v3: C[M,N] = A[M,K] @ Bt[N,K]^T   (A, Bt both K-major, pre-rounded)
// Block 128x128, BK=32, 256 threads (8 warps 4x2, warp tile 32x64).
// 3-stage cp.async pipeline; ALL fragments via ldmatrix.x4.
// ---------------------------------------------------------------------------
#define GSTR 36                         // smem row stride in floats (144 B)
#define GSTRB (GSTR*4)
#define TILE_FL (128 * GSTR)            // 4608 floats per operand tile
#define STG_FL (2 * TILE_FL)            // 9216 floats / stage (A + B)
#define NSTG 3
#define GEMM_SMEM (NSTG * STG_FL * 4)   // 110592 B -> 2 CTAs/SM

__global__ __launch_bounds__(256, 2) void gemm_tf32_kernel(
    const float* __restrict__ A, const float* __restrict__ Bt,
    float* __restrict__ C, int M, int N, int K,
    int lda, int ldb, int ldc, int roundOut)
{
    extern __shared__ float sm[];
    const uint32_t sm_u32 = (uint32_t)__cvta_generic_to_shared(sm);

    const int tid  = threadIdx.x;
    const int lane = tid & 31, warp = tid >> 5;
    const int g = lane >> 2, t4 = lane & 3;
    const int wm = warp >> 1, wn = warp & 1;
    const int bm = blockIdx.y * 128, bn = blockIdx.x * 128;

    // ldmatrix lane roles
    const int lm = lane >> 3, rr = lane & 7;
    // A matrices: m0: rows+0 w0-3 | m1: rows+8 w0-3 | m2: rows+0 w4-7 | m3: rows+8 w4-7
    const uint32_t aoff = (uint32_t)((wm * 32 + (lm & 1) * 8 + rr) * GSTRB + (lm >> 1) * 16);
    // B matrices: m0: ni0 b0 | m1: ni0 b1 | m2: ni1 b0 | m3: ni1 b1
    const uint32_t boff = (uint32_t)((wn * 64 + (lm >> 1) * 8 + rr) * GSTRB + (lm & 1) * 16);

    // loader: thread -> row tid>>3 (+32p), 16B chunk tid&7  (identical A/B shape)
    const int lrow = tid >> 3, lchk = tid & 7;
    const int ktiles = K / 32;

    float acc[2][8][4];
#pragma unroll
    for (int mi = 0; mi < 2; mi++)
#pragma unroll
        for (int ni = 0; ni < 8; ni++)
#pragma unroll
            for (int e = 0; e < 4; e++) acc[mi][ni][e] = 0.f;

    auto issue = [&](int stg, int t) {
        if (t < ktiles) {
            float* As = sm + stg * STG_FL;
            float* Bs = As + TILE_FL;
            const int kc = t * 32 + lchk * 4;
#pragma unroll
            for (int p = 0; p < 4; p++) {
                int row = lrow + p * 32;
                cp_async16(&As[row * GSTR + lchk * 4],
                           &A[(size_t)(bm + row) * lda + kc]);
                cp_async16(&Bs[row * GSTR + lchk * 4],
                           &Bt[(size_t)(bn + row) * ldb + kc]);
            }
        }
        cp_commit();
    };

    issue(0, 0);
    issue(1, 1);

    for (int t = 0; t < ktiles; t++) {
        cp_wait<1>();
        __syncthreads();
        issue((t + 2) % NSTG, t + 2);

        const uint32_t aBase = sm_u32 + (uint32_t)((t % NSTG) * STG_FL * 4) + aoff;
        const uint32_t bBase = aBase - aoff + (uint32_t)(TILE_FL * 4) + boff;

#pragma unroll
        for (int ks = 0; ks < 4; ks++) {
            uint32_t a[2][4], b[4][4];
#pragma unroll
            for (int mi = 0; mi < 2; mi++)
                ldsm_x4(a[mi], aBase + mi * 16 * GSTRB + ks * 32);
#pragma unroll
            for (int p = 0; p < 4; p++)
                ldsm_x4(b[p], bBase + p * 16 * GSTRB + ks * 32);
#pragma unroll
            for (int mi = 0; mi < 2; mi++)
#pragma unroll
                for (int ni = 0; ni < 8; ni++)
                    mma_tf32(acc[mi][ni], a[mi], &b[ni >> 1][(ni & 1) * 2], acc[mi][ni]);
        }
    }

#pragma unroll
    for (int mi = 0; mi < 2; mi++)
#pragma unroll
        for (int ni = 0; ni < 8; ni++) {
            float v0 = acc[mi][ni][0], v1 = acc[mi][ni][1];
            float v2 = acc[mi][ni][2], v3 = acc[mi][ni][3];
            if (roundOut) {
                v0 = f2tf32(v0); v1 = f2tf32(v1);
                v2 = f2tf32(v2); v3 = f2tf32(v3);
            }
            int r0 = bm + wm * 32 + mi * 16 + g;
            int cc = bn + wn * 64 + ni * 8 + t4 * 2;
            *reinterpret_cast<float2*>(&C[(size_t)r0 * ldc + cc]) = make_float2(v0, v1);
            *reinterpret_cast<float2*>(&C[(size_t)(r0 + 8) * ldc + cc]) = make_float2(v2, v3);
        }
}

// ---------------------------------------------------------------------------
// RoPE (interleaved pairs), in-place; output tf32-rounded.
// ---------------------------------------------------------------------------
__global__ void rope_kernel(float* __restrict__ t, const float* __restrict__ fc,
                            const float* __restrict__ fs, int nheads)
{
    int idx = blockIdx.x * blockDim.x + threadIdx.x;
    int fi = idx & 63;
    int hp = idx >> 6;
    int head = hp % nheads;
    int row = hp / nheads;
    int s = row & (SEQLEN - 1);
    float c = fc[s * 64 + fi], sn = fs[s * 64 + fi];
    float2* p = reinterpret_cast<float2*>(
        &t[(size_t)row * (nheads * HD) + head * HD + fi * 2]);
    float2 v = *p;
    *p = make_float2(f2tf32(v.x * c - v.y * sn), f2tf32(v.x * sn + v.y * c));
}

// ---------------------------------------------------------------------------
// Flash attention (causal, GQA) — unchanged from R4 (verified).
// ---------------------------------------------------------------------------
#define ATS 140
#define AT_FL (64 * ATS)
#define ATTN_SMEM (6 * AT_FL * 4)

__global__ __launch_bounds__(128) void attn_kernel(
    const float* __restrict__ Q, const float* __restrict__ Kg,
    const float* __restrict__ Vg, float* __restrict__ ctx)
{
    extern __shared__ float sm[];
    float* Qs  = sm;
    float* Ksb[2] = { sm + AT_FL,     sm + 2 * AT_FL };
    float* Vsb[2] = { sm + 3 * AT_FL, sm + 4 * AT_FL };
    float* Ps  = sm + 5 * AT_FL;

    const int qt = blockIdx.x, h = blockIdx.y, b = blockIdx.z;
    const int hkv = h >> 2;
    const int tid = threadIdx.x, lane = tid & 31, warp = tid >> 5;
    const int g = lane >> 2, t4 = lane & 3;

    const int lr = tid >> 5;
    const int lc = (tid & 31) * 4;

#pragma unroll
    for (int p = 0; p < 16; p++) {
        int r = lr + p * 4;
        int gr = b * SEQLEN + qt * 64 + r;
        *reinterpret_cast<float4*>(&Qs[r * ATS + lc]) =
            *reinterpret_cast<const float4*>(&Q[(size_t)gr * DIM + h * HD + lc]);
    }

    auto issue_kv = [&](int buf, int j) {
        float* Ks = Ksb[buf];
        float* Vs = Vsb[buf];
#pragma unroll
        for (int p = 0; p < 16; p++) {
            int r = lr + p * 4;
            int gr = b * SEQLEN + j * 64 + r;
            cp_async16(&Ks[r * ATS + lc], &Kg[(size_t)gr * KVDIM + hkv * HD + lc]);
            cp_async16(&Vs[r * ATS + lc], &Vg[(size_t)gr * KVDIM + hkv * HD + lc]);
        }
        cp_commit();
    };

    float m_s[2] = {-1e30f, -1e30f};
    float l_s[2] = {0.f, 0.f};
    float o[16][4];
#pragma unroll
    for (int di = 0; di < 16; di++)
#pragma unroll
        for (int e = 0; e < 4; e++) o[di][e] = 0.f;

    const float scale = 0.08838834764831845f;

    issue_kv(0, 0);

    for (int j = 0; j <= qt; j++) {
        cp_wait<0>();
        __syncthreads();
        if (j + 1 <= qt) issue_kv((j + 1) & 1, j + 1);

        const float* Ks = Ksb[j & 1];
        const float* Vs = Vsb[j & 1];

        float s[8][4];
#pragma unroll
        for (int ni = 0; ni < 8; ni++)
#pragma unroll
            for (int e = 0; e < 4; e++) s[ni][e] = 0.f;

#pragma unroll
        for (int ks = 0; ks < 16; ks++) {
            float a[4];
            int r0 = warp * 16 + g;
            a[0] = Qs[r0 * ATS + ks * 8 + t4];
            a[1] = Qs[(r0 + 8) * ATS + ks * 8 + t4];
            a[2] = Qs[r0 * ATS + ks * 8 + t4 + 4];
            a[3] = Qs[(r0 + 8) * ATS + ks * 8 + t4 + 4];
#pragma unroll
            for (int ni = 0; ni < 8; ni++) {
                float bf[2];
                bf[0] = Ks[(ni * 8 + g) * ATS + ks * 8 + t4];
                bf[1] = Ks[(ni * 8 + g) * ATS + ks * 8 + t4 + 4];
                mma_tf32f(s[ni], a, bf, s[ni]);
            }
        }

#pragma unroll
        for (int ni = 0; ni < 8; ni++)
#pragma unroll
            for (int e = 0; e < 4; e++) s[ni][e] *= scale;
        if (j == qt) {
#pragma unroll
            for (int ni = 0; ni < 8; ni++)
#pragma unroll
                for (int e = 0; e < 4; e++) {
                    int qr = warp * 16 + g + (e >> 1) * 8;
                    int kc = ni * 8 + t4 * 2 + (e & 1);
                    if (kc > qr) s[ni][e] = -1e30f;
                }
        }

#pragma unroll
        for (int rr = 0; rr < 2; rr++) {
            float mx = -1e30f;
#pragma unroll
            for (int ni = 0; ni < 8; ni++)
                mx = fmaxf(mx, fmaxf(s[ni][rr * 2], s[ni][rr * 2 + 1]));
            mx = fmaxf(mx, __shfl_xor_sync(0xffffffffu, mx, 1));
            mx = fmaxf(mx, __shfl_xor_sync(0xffffffffu, mx, 2));
            float nm = fmaxf(m_s[rr], mx);
            float alpha = __expf(m_s[rr] - nm);
            m_s[rr] = nm;
            float rsum = 0.f;
#pragma unroll
            for (int ni = 0; ni < 8; ni++) {
#pragma unroll
                for (int cc = 0; cc < 2; cc++) {
                    float pv = __expf(s[ni][rr * 2 + cc] - nm);
                    s[ni][rr * 2 + cc] = pv;
                    rsum += pv;
                }
            }
            rsum += __shfl_xor_sync(0xffffffffu, rsum, 1);
            rsum += __shfl_xor_sync(0xffffffffu, rsum, 2);
            l_s[rr] = l_s[rr] * alpha + rsum;
#pragma unroll
            for (int di = 0; di < 16; di++) {
                o[di][rr * 2] *= alpha;
                o[di][rr * 2 + 1] *= alpha;
            }
        }

        __syncwarp();
#pragma unroll
        for (int ni = 0; ni < 8; ni++)
#pragma unroll
            for (int e = 0; e < 4; e++) {
                int pr = warp * 16 + g + (e >> 1) * 8;
                int pc = ni * 8 + t4 * 2 + (e & 1);
                Ps[pr * ATS + pc] = f2tf32(s[ni][e]);
            }
        __syncwarp();

#pragma unroll
        for (int ks = 0; ks < 8; ks++) {
            float a[4];
            int r0 = warp * 16 + g;
            a[0] = Ps[r0 * ATS + ks * 8 + t4];
            a[1] = Ps[(r0 + 8) * ATS + ks * 8 + t4];
            a[2] = Ps[r0 * ATS + ks * 8 + t4 + 4];
            a[3] = Ps[(r0 + 8) * ATS + ks * 8 + t4 + 4];
#pragma unroll
            for (int di = 0; di < 16; di++) {
                float bf[2];
                bf[0] = Vs[(ks * 8 + t4) * ATS + di * 8 + g];
                bf[1] = Vs[(ks * 8 + t4 + 4) * ATS + di * 8 + g];
                mma_tf32f(o[di], a, bf, o[di]);
            }
        }
    }

#pragma unroll
    for (int rr = 0; rr < 2; rr++) {
        float inv = 1.0f / l_s[rr];
        int gr = b * SEQLEN + qt * 64 + warp * 16 + g + rr * 8;
#pragma unroll
        for (int di = 0; di < 16; di++) {
            float2 v = make_float2(f2tf32(o[di][rr * 2] * inv),
                                   f2tf32(o[di][rr * 2 + 1] * inv));
            *reinterpret_cast<float2*>(
                &ctx[(size_t)gr * DIM + h * HD + di * 8 + t4 * 2]) = v;
        }
    }
}

// ---------------------------------------------------------------------------
// launch
// ---------------------------------------------------------------------------
extern "C" void kernel_launch(void* const* d_in, const int* in_sizes, int n_in,
                              void* d_out, int out_size)
{
    const float* x  = (const float*)d_in[0];
    const float* wq = (const float*)d_in[1];
    const float* wk = (const float*)d_in[2];
    const float* wv = (const float*)d_in[3];
    const float* wo = (const float*)d_in[4];
    const float* fc = (const float*)d_in[5];
    const float* fs = (const float*)d_in[6];
    // d_in[7] = mask (causal, applied analytically), d_in[8] = start_pos (0)
    float* out = (float*)d_out;

    float *q, *k, *v, *ctx, *xt, *wqt, *wkt, *wvt, *wot;
    cudaGetSymbolAddress((void**)&q,   g_q);
    cudaGetSymbolAddress((void**)&k,   g_k);
    cudaGetSymbolAddress((void**)&v,   g_v);
    cudaGetSymbolAddress((void**)&ctx, g_ctx);
    cudaGetSymbolAddress((void**)&xt,  g_xt);
    cudaGetSymbolAddress((void**)&wqt, g_wqt);
    cudaGetSymbolAddress((void**)&wkt, g_wkt);
    cudaGetSymbolAddress((void**)&wvt, g_wvt);
    cudaGetSymbolAddress((void**)&wot, g_wot);

    cudaFuncSetAttribute(gemm_tf32_kernel,
                         cudaFuncAttributeMaxDynamicSharedMemorySize, GEMM_SMEM);
    cudaFuncSetAttribute(attn_kernel,
                         cudaFuncAttributeMaxDynamicSharedMemorySize, ATTN_SMEM);

    // A-operand rounding (x) + fused transpose+round of weights -> [N,K]
    int n4_big = MROWS * DIM / 4;
    cvt_tf32_kernel<<<(n4_big + 255) / 256, 256>>>((const float4*)x, (float4*)xt, n4_big);
    transpose_cvt_kernel<<<dim3(DIM / 32,   DIM / 32), dim3(32, 8)>>>(wq, wqt, DIM, DIM);
    transpose_cvt_kernel<<<dim3(KVDIM / 32, DIM / 32), dim3(32, 8)>>>(wk, wkt, DIM, KVDIM);
    transpose_cvt_kernel<<<dim3(KVDIM / 32, DIM / 32), dim3(32, 8)>>>(wv, wvt, DIM, KVDIM);
    transpose_cvt_kernel<<<dim3(DIM / 32,   DIM / 32), dim3(32, 8)>>>(wo, wot, DIM, DIM);

    // QKV projections (V output rounded for attention mma)
    gemm_tf32_kernel<<<dim3(DIM / 128,   MROWS / 128), 256, GEMM_SMEM>>>(
        xt, wqt, q, MROWS, DIM,   DIM, DIM, DIM, DIM,   0);
    gemm_tf32_kernel<<<dim3(KVDIM / 128, MROWS / 128), 256, GEMM_SMEM>>>(
        xt, wkt, k, MROWS, KVDIM, DIM, DIM, DIM, KVDIM, 0);
    gemm_tf32_kernel<<<dim3(KVDIM / 128, MROWS / 128), 256, GEMM_SMEM>>>(
        xt, wvt, v, MROWS, KVDIM, DIM, DIM, DIM, KVDIM, 1);

    // RoPE on Q and K (outputs tf32-rounded)
    rope_kernel<<<(MROWS * NHEADS * 64) / 256, 256>>>(q, fc, fs, NHEADS);
    rope_kernel<<<(MROWS * NKV * 64) / 256, 256>>>(k, fc, fs, NKV);

    // Causal flash attention (ctx written tf32-rounded)
    attn_kernel<<<dim3(SEQLEN / 64, NHEADS, BSZ), 128, ATTN_SMEM>>>(q, k, v, ctx);

    // Output projection
    gemm_tf32_kernel<<<dim3(DIM / 128, MROWS / 128), 256, GEMM_SMEM>>>(
        ctx, wot, out, MROWS, DIM, DIM, DIM, DIM, DIM, 0);
}

// round 8
// speedup vs baseline: 1.7141x; 1.0352x over previous
#include <cuda_runtime.h>
#include <cuda_bf16.h>
#include <cstdint>

// Problem constants
#define BSZ      2
#define SEQLEN   2048
#define DIM      4096
#define NHEADS   32
#define NKV      8
#define HD       128
#define MROWS    (BSZ*SEQLEN)          // 4096
#define KVDIM    (NKV*HD)              // 1024

// Scratch (device globals: allocation-free rule)
__device__ float g_q[MROWS * DIM];
__device__ float g_k[MROWS * KVDIM];
__device__ float g_v[MROWS * KVDIM];
__device__ float g_vt[KVDIM * MROWS];        // V^T: [d_global][token], tf32-rounded
__device__ float g_ctx[MROWS * DIM];
// tf32-pre-rounded A operand + transposed tf32 weights ([N,K] K-major)
__device__ float g_xt[MROWS * DIM];
__device__ float g_wqt[DIM * DIM];
__device__ float g_wkt[DIM * KVDIM];
__device__ float g_wvt[DIM * KVDIM];
__device__ float g_wot[DIM * DIM];

// ---------------------------------------------------------------------------
// helpers
// ---------------------------------------------------------------------------
__device__ __forceinline__ float f2tf32(float x) {
    float y;
    asm("cvt.rna.tf32.f32 %0, %1;" : "=f"(y) : "f"(x));
    return y;
}

__device__ __forceinline__ void mma_tf32(float d[4], const uint32_t a[4],
                                         const uint32_t b[2], const float c[4]) {
    asm volatile(
        "mma.sync.aligned.m16n8k8.row.col.f32.tf32.tf32.f32 "
        "{%0,%1,%2,%3}, {%4,%5,%6,%7}, {%8,%9}, {%10,%11,%12,%13};\n"
        : "=f"(d[0]), "=f"(d[1]), "=f"(d[2]), "=f"(d[3])
        : "r"(a[0]), "r"(a[1]), "r"(a[2]), "r"(a[3]),
          "r"(b[0]), "r"(b[1]),
          "f"(c[0]), "f"(c[1]), "f"(c[2]), "f"(c[3]));
}

__device__ __forceinline__ void ldsm_x4(uint32_t d[4], uint32_t addr) {
    asm volatile(
        "ldmatrix.sync.aligned.m8n8.x4.shared.b16 {%0,%1,%2,%3}, [%4];"
        : "=r"(d[0]), "=r"(d[1]), "=r"(d[2]), "=r"(d[3]) : "r"(addr));
}

__device__ __forceinline__ void cp_async16(void* smem, const void* gmem) {
    uint32_t s = (uint32_t)__cvta_generic_to_shared(smem);
    asm volatile("cp.async.cg.shared.global [%0], [%1], 16;\n" :: "r"(s), "l"(gmem));
}
__device__ __forceinline__ void cp_commit() {
    asm volatile("cp.async.commit_group;\n" ::: "memory");
}
template<int N> __device__ __forceinline__ void cp_wait() {
    asm volatile("cp.async.wait_group %0;\n" :: "n"(N) : "memory");
}

// ---------------------------------------------------------------------------
// Elementwise tf32 pre-rounding (x)
// ---------------------------------------------------------------------------
__global__ void cvt_tf32_kernel(const float4* __restrict__ in,
                                float4* __restrict__ out, int n4)
{
    int i = blockIdx.x * blockDim.x + threadIdx.x;
    if (i < n4) {
        float4 v = in[i];
        v.x = f2tf32(v.x); v.y = f2tf32(v.y); v.z = f2tf32(v.z); v.w = f2tf32(v.w);
        out[i] = v;
    }
}

// ---------------------------------------------------------------------------
// Fused transpose + tf32 round: in[K,N] -> out[N,K]
// ---------------------------------------------------------------------------
__global__ void transpose_cvt_kernel(const float* __restrict__ in,
                                     float* __restrict__ out, int K, int N)
{
    __shared__ float t[32][33];
    int k0 = blockIdx.y * 32, n0 = blockIdx.x * 32;
    int tx = threadIdx.x, ty = threadIdx.y;
#pragma unroll
    for (int i = 0; i < 4; i++)
        t[ty + 8 * i][tx] = in[(size_t)(k0 + ty + 8 * i) * N + n0 + tx];
    __syncthreads();
#pragma unroll
    for (int i = 0; i < 4; i++)
        out[(size_t)(n0 + ty + 8 * i) * K + k0 + tx] = f2tf32(t[tx][ty + 8 * i]);
}

// ---------------------------------------------------------------------------
// TF32 GEMM v3 (unchanged from R6): C[M,N] = A[M,K] @ Bt[N,K]^T
// ---------------------------------------------------------------------------
#define GSTR 36
#define GSTRB (GSTR*4)
#define TILE_FL (128 * GSTR)
#define STG_FL (2 * TILE_FL)
#define NSTG 3
#define GEMM_SMEM (NSTG * STG_FL * 4)

__global__ __launch_bounds__(256, 2) void gemm_tf32_kernel(
    const float* __restrict__ A, const float* __restrict__ Bt,
    float* __restrict__ C, int M, int N, int K,
    int lda, int ldb, int ldc, int roundOut)
{
    extern __shared__ float sm[];
    const uint32_t sm_u32 = (uint32_t)__cvta_generic_to_shared(sm);

    const int tid  = threadIdx.x;
    const int lane = tid & 31, warp = tid >> 5;
    const int g = lane >> 2, t4 = lane & 3;
    const int wm = warp >> 1, wn = warp & 1;
    const int bm = blockIdx.y * 128, bn = blockIdx.x * 128;

    const int lm = lane >> 3, rr = lane & 7;
    const uint32_t aoff = (uint32_t)((wm * 32 + (lm & 1) * 8 + rr) * GSTRB + (lm >> 1) * 16);
    const uint32_t boff = (uint32_t)((wn * 64 + (lm >> 1) * 8 + rr) * GSTRB + (lm & 1) * 16);

    const int lrow = tid >> 3, lchk = tid & 7;
    const int ktiles = K / 32;

    float acc[2][8][4];
#pragma unroll
    for (int mi = 0; mi < 2; mi++)
#pragma unroll
        for (int ni = 0; ni < 8; ni++)
#pragma unroll
            for (int e = 0; e < 4; e++) acc[mi][ni][e] = 0.f;

    auto issue = [&](int stg, int t) {
        if (t < ktiles) {
            float* As = sm + stg * STG_FL;
            float* Bs = As + TILE_FL;
            const int kc = t * 32 + lchk * 4;
#pragma unroll
            for (int p = 0; p < 4; p++) {
                int row = lrow + p * 32;
                cp_async16(&As[row * GSTR + lchk * 4],
                           &A[(size_t)(bm + row) * lda + kc]);
                cp_async16(&Bs[row * GSTR + lchk * 4],
                           &Bt[(size_t)(bn + row) * ldb + kc]);
            }
        }
        cp_commit();
    };

    issue(0, 0);
    issue(1, 1);

    for (int t = 0; t < ktiles; t++) {
        cp_wait<1>();
        __syncthreads();
        issue((t + 2) % NSTG, t + 2);

        const uint32_t aBase = sm_u32 + (uint32_t)((t % NSTG) * STG_FL * 4) + aoff;
        const uint32_t bBase = aBase - aoff + (uint32_t)(TILE_FL * 4) + boff;

#pragma unroll
        for (int ks = 0; ks < 4; ks++) {
            uint32_t a[2][4], b[4][4];
#pragma unroll
            for (int mi = 0; mi < 2; mi++)
                ldsm_x4(a[mi], aBase + mi * 16 * GSTRB + ks * 32);
#pragma unroll
            for (int p = 0; p < 4; p++)
                ldsm_x4(b[p], bBase + p * 16 * GSTRB + ks * 32);
#pragma unroll
            for (int mi = 0; mi < 2; mi++)
#pragma unroll
                for (int ni = 0; ni < 8; ni++)
                    mma_tf32(acc[mi][ni], a[mi], &b[ni >> 1][(ni & 1) * 2], acc[mi][ni]);
        }
    }

#pragma unroll
    for (int mi = 0; mi < 2; mi++)
#pragma unroll
        for (int ni = 0; ni < 8; ni++) {
            float v0 = acc[mi][ni][0], v1 = acc[mi][ni][1];
            float v2 = acc[mi][ni][2], v3 = acc[mi][ni][3];
            if (roundOut) {
                v0 = f2tf32(v0); v1 = f2tf32(v1);
                v2 = f2tf32(v2); v3 = f2tf32(v3);
            }
            int r0 = bm + wm * 32 + mi * 16 + g;
            int cc = bn + wn * 64 + ni * 8 + t4 * 2;
            *reinterpret_cast<float2*>(&C[(size_t)r0 * ldc + cc]) = make_float2(v0, v1);
            *reinterpret_cast<float2*>(&C[(size_t)(r0 + 8) * ldc + cc]) = make_float2(v2, v3);
        }
}

// ---------------------------------------------------------------------------
// RoPE (interleaved pairs), in-place; output tf32-rounded.
// ---------------------------------------------------------------------------
__global__ void rope_kernel(float* __restrict__ t, const float* __restrict__ fc,
                            const float* __restrict__ fs, int nheads)
{
    int idx = blockIdx.x * blockDim.x + threadIdx.x;
    int fi = idx & 63;
    int hp = idx >> 6;
    int head = hp % nheads;
    int row = hp / nheads;
    int s = row & (SEQLEN - 1);
    float c = fc[s * 64 + fi], sn = fs[s * 64 + fi];
    float2* p = reinterpret_cast<float2*>(
        &t[(size_t)row * (nheads * HD) + head * HD + fi * 2]);
    float2 v = *p;
    *p = make_float2(f2tf32(v.x * c - v.y * sn), f2tf32(v.x * sn + v.y * c));
}

// ---------------------------------------------------------------------------
// Flash attention v2 (causal, GQA): full-ldmatrix fragment loads.
// One CTA = 64 q rows of one (b,h); 4 warps x 16 q rows; 64-key j-tiles.
// K smem [key][d] (n-major) -> ldsm B frags directly.
// V^T smem [d][key] (from pre-transposed g_vt) -> ldsm B frags for PV.
// ---------------------------------------------------------------------------
#define ATS2 132                  // Q/K/P smem row stride (132 mod 32 = 4)
#define QK_FL (64 * ATS2)         // 8448 floats
#define VT_STR 68                 // V^T smem row stride (68 mod 32 = 4)
#define VT_FL (128 * VT_STR)      // 8704 floats
#define ATTN_SMEM ((4 * QK_FL + 2 * VT_FL) * 4)   // 204800 B

__global__ __launch_bounds__(128) void attn_kernel(
    const float* __restrict__ Q, const float* __restrict__ Kg,
    const float* __restrict__ Vt, float* __restrict__ ctx)
{
    extern __shared__ float sm[];
    float* Qs     = sm;
    float* Ksb[2] = { sm + QK_FL, sm + 2 * QK_FL };
    float* Vsb[2] = { sm + 3 * QK_FL, sm + 3 * QK_FL + VT_FL };
    float* Ps     = sm + 3 * QK_FL + 2 * VT_FL;
    const uint32_t sm_u32 = (uint32_t)__cvta_generic_to_shared(sm);
    const uint32_t qs_u = sm_u32;
    const uint32_t ks_u[2] = { sm_u32 + QK_FL * 4, sm_u32 + 2 * QK_FL * 4 };
    const uint32_t vs_u[2] = { sm_u32 + 3 * QK_FL * 4, sm_u32 + (3 * QK_FL + VT_FL) * 4 };
    const uint32_t ps_u = sm_u32 + (3 * QK_FL + 2 * VT_FL) * 4;

    const int qt = blockIdx.x, h = blockIdx.y, b = blockIdx.z;
    const int hkv = h >> 2;
    const int tid = threadIdx.x, lane = tid & 31, warp = tid >> 5;
    const int g = lane >> 2, t4 = lane & 3;
    const int lm = lane >> 3, rr = lane & 7;

    // ldmatrix fixed offsets (bytes)
    const uint32_t aoff = (uint32_t)((warp * 16 + (lm & 1) * 8 + rr) * ATS2 * 4 + (lm >> 1) * 16);
    const uint32_t koff = (uint32_t)(((lm >> 1) * 8 + rr) * ATS2 * 4 + (lm & 1) * 16);
    const uint32_t voff = (uint32_t)(((lm >> 1) * 8 + rr) * VT_STR * 4 + (lm & 1) * 16);

    const int lr = tid >> 5;          // 0..3
    const int lc = (tid & 31) * 4;    // 0..124

    // Load Q tile (64 x 128), already tf32-rounded by rope
#pragma unroll
    for (int p = 0; p < 16; p++) {
        int r = lr + p * 4;
        int gr = b * SEQLEN + qt * 64 + r;
        *reinterpret_cast<float4*>(&Qs[r * ATS2 + lc]) =
            *reinterpret_cast<const float4*>(&Q[(size_t)gr * DIM + h * HD + lc]);
    }

    auto issue_kv = [&](int buf, int j) {
        float* Ks = Ksb[buf];
        float* Vs = Vsb[buf];
#pragma unroll
        for (int p = 0; p < 16; p++) {
            int r = lr + p * 4;
            int gr = b * SEQLEN + j * 64 + r;
            cp_async16(&Ks[r * ATS2 + lc], &Kg[(size_t)gr * KVDIM + hkv * HD + lc]);
        }
        // V^T tile: 128 d-rows x 64 keys; one d-row per thread, 16 x 16B chunks
        const float* vsrc = &Vt[(size_t)(hkv * HD + tid) * MROWS + b * SEQLEN + j * 64];
#pragma unroll
        for (int c = 0; c < 16; c++)
            cp_async16(&Vs[tid * VT_STR + c * 4], vsrc + c * 4);
        cp_commit();
    };

    float m_s[2] = {-1e30f, -1e30f};
    float l_s[2] = {0.f, 0.f};
    float o[16][4];
#pragma unroll
    for (int di = 0; di < 16; di++)
#pragma unroll
        for (int e = 0; e < 4; e++) o[di][e] = 0.f;

    const float scale = 0.08838834764831845f;

    issue_kv(0, 0);

    for (int j = 0; j <= qt; j++) {
        cp_wait<0>();
        __syncthreads();
        if (j + 1 <= qt) issue_kv((j + 1) & 1, j + 1);

        const uint32_t kb = ks_u[j & 1] + koff;
        const uint32_t vb = vs_u[j & 1] + voff;
        const uint32_t qb = qs_u + aoff;

        // S = Q @ K^T : 16 k-steps (d), 8 n-tiles (64 keys)
        float s[8][4];
#pragma unroll
        for (int ni = 0; ni < 8; ni++)
#pragma unroll
            for (int e = 0; e < 4; e++) s[ni][e] = 0.f;

#pragma unroll
        for (int ks = 0; ks < 16; ks++) {
            uint32_t a[4], kf[4][4];
            ldsm_x4(a, qb + ks * 32);
#pragma unroll
            for (int p = 0; p < 4; p++)
                ldsm_x4(kf[p], kb + p * 16 * ATS2 * 4 + ks * 32);
#pragma unroll
            for (int ni = 0; ni < 8; ni++)
                mma_tf32(s[ni], a, &kf[ni >> 1][(ni & 1) * 2], s[ni]);
        }

        // scale + causal mask (diagonal tile only)
#pragma unroll
        for (int ni = 0; ni < 8; ni++)
#pragma unroll
            for (int e = 0; e < 4; e++) s[ni][e] *= scale;
        if (j == qt) {
#pragma unroll
            for (int ni = 0; ni < 8; ni++)
#pragma unroll
                for (int e = 0; e < 4; e++) {
                    int qr = warp * 16 + g + (e >> 1) * 8;
                    int kc = ni * 8 + t4 * 2 + (e & 1);
                    if (kc > qr) s[ni][e] = -1e30f;
                }
        }

        // online softmax (thread rows g, g+8 of warp tile)
#pragma unroll
        for (int rr2 = 0; rr2 < 2; rr2++) {
            float mx = -1e30f;
#pragma unroll
            for (int ni = 0; ni < 8; ni++)
                mx = fmaxf(mx, fmaxf(s[ni][rr2 * 2], s[ni][rr2 * 2 + 1]));
            mx = fmaxf(mx, __shfl_xor_sync(0xffffffffu, mx, 1));
            mx = fmaxf(mx, __shfl_xor_sync(0xffffffffu, mx, 2));
            float nm = fmaxf(m_s[rr2], mx);
            float alpha = __expf(m_s[rr2] - nm);
            m_s[rr2] = nm;
            float rsum = 0.f;
#pragma unroll
            for (int ni = 0; ni < 8; ni++) {
#pragma unroll
                for (int cc = 0; cc < 2; cc++) {
                    float pv = __expf(s[ni][rr2 * 2 + cc] - nm);
                    s[ni][rr2 * 2 + cc] = pv;
                    rsum += pv;
                }
            }
            rsum += __shfl_xor_sync(0xffffffffu, rsum, 1);
            rsum += __shfl_xor_sync(0xffffffffu, rsum, 2);
            l_s[rr2] = l_s[rr2] * alpha + rsum;
#pragma unroll
            for (int di = 0; di < 16; di++) {
                o[di][rr2 * 2] *= alpha;
                o[di][rr2 * 2 + 1] *= alpha;
            }
        }

        __syncwarp();
        // stage P (tf32) in smem, warp-private rows
#pragma unroll
        for (int ni = 0; ni < 8; ni++)
#pragma unroll
            for (int e = 0; e < 4; e++) {
                int pr = warp * 16 + g + (e >> 1) * 8;
                int pc = ni * 8 + t4 * 2 + (e & 1);
                Ps[pr * ATS2 + pc] = f2tf32(s[ni][e]);
            }
        __syncwarp();

        // O += P @ V : 8 k-steps (keys), 16 n-tiles (128 d)
        const uint32_t pb = ps_u + aoff;
#pragma unroll
        for (int ks = 0; ks < 8; ks++) {
            uint32_t a[4], vf[8][4];
            ldsm_x4(a, pb + ks * 32);
#pragma unroll
            for (int p = 0; p < 8; p++)
                ldsm_x4(vf[p], vb + p * 16 * VT_STR * 4 + ks * 32);
#pragma unroll
            for (int di = 0; di < 16; di++)
                mma_tf32(o[di], a, &vf[di >> 1][(di & 1) * 2], o[di]);
        }
    }

    // normalize + tf32-round + write ctx [row][h*128+d]
#pragma unroll
    for (int rr2 = 0; rr2 < 2; rr2++) {
        float inv = 1.0f / l_s[rr2];
        int gr = b * SEQLEN + qt * 64 + warp * 16 + g + rr2 * 8;
#pragma unroll
        for (int di = 0; di < 16; di++) {
            float2 v = make_float2(f2tf32(o[di][rr2 * 2] * inv),
                                   f2tf32(o[di][rr2 * 2 + 1] * inv));
            *reinterpret_cast<float2*>(
                &ctx[(size_t)gr * DIM + h * HD + di * 8 + t4 * 2]) = v;
        }
    }
}

// ---------------------------------------------------------------------------
// launch
// ---------------------------------------------------------------------------
extern "C" void kernel_launch(void* const* d_in, const int* in_sizes, int n_in,
                              void* d_out, int out_size)
{
    const float* x  = (const float*)d_in[0];
    const float* wq = (const float*)d_in[1];
    const float* wk = (const float*)d_in[2];
    const float* wv = (const float*)d_in[3];
    const float* wo = (const float*)d_in[4];
    const float* fc = (const float*)d_in[5];
    const float* fs = (const float*)d_in[6];
    // d_in[7] = mask (causal, applied analytically), d_in[8] = start_pos (0)
    float* out = (float*)d_out;

    float *q, *k, *v, *vt, *ctx, *xt, *wqt, *wkt, *wvt, *wot;
    cudaGetSymbolAddress((void**)&q,   g_q);
    cudaGetSymbolAddress((void**)&k,   g_k);
    cudaGetSymbolAddress((void**)&v,   g_v);
    cudaGetSymbolAddress((void**)&vt,  g_vt);
    cudaGetSymbolAddress((void**)&ctx, g_ctx);
    cudaGetSymbolAddress((void**)&xt,  g_xt);
    cudaGetSymbolAddress((void**)&wqt, g_wqt);
    cudaGetSymbolAddress((void**)&wkt, g_wkt);
    cudaGetSymbolAddress((void**)&wvt, g_wvt);
    cudaGetSymbolAddress((void**)&wot, g_wot);

    cudaFuncSetAttribute(gemm_tf32_kernel,
                         cudaFuncAttributeMaxDynamicSharedMemorySize, GEMM_SMEM);
    cudaFuncSetAttribute(attn_kernel,
                         cudaFuncAttributeMaxDynamicSharedMemorySize, ATTN_SMEM);

    // A-operand rounding (x) + fused transpose+round of weights -> [N,K]
    int n4_big = MROWS * DIM / 4;
    cvt_tf32_kernel<<<(n4_big + 255) / 256, 256>>>((const float4*)x, (float4*)xt, n4_big);
    transpose_cvt_kernel<<<dim3(DIM / 32,   DIM / 32), dim3(32, 8)>>>(wq, wqt, DIM, DIM);
    transpose_cvt_kernel<<<dim3(KVDIM / 32, DIM / 32), dim3(32, 8)>>>(wk, wkt, DIM, KVDIM);
    transpose_cvt_kernel<<<dim3(KVDIM / 32, DIM / 32), dim3(32, 8)>>>(wv, wvt, DIM, KVDIM);
    transpose_cvt_kernel<<<dim3(DIM / 32,   DIM / 32), dim3(32, 8)>>>(wo, wot, DIM, DIM);

    // QKV projections
    gemm_tf32_kernel<<<dim3(DIM / 128,   MROWS / 128), 256, GEMM_SMEM>>>(
        xt, wqt, q, MROWS, DIM,   DIM, DIM, DIM, DIM,   0);
    gemm_tf32_kernel<<<dim3(KVDIM / 128, MROWS / 128), 256, GEMM_SMEM>>>(
        xt, wkt, k, MROWS, KVDIM, DIM, DIM, DIM, KVDIM, 0);
    gemm_tf32_kernel<<<dim3(KVDIM / 128, MROWS / 128), 256, GEMM_SMEM>>>(
        xt, wvt, v, MROWS, KVDIM, DIM, DIM, DIM, KVDIM, 0);

    // V^T for ldmatrix B-fragments in attention (rounding applied here)
    transpose_cvt_kernel<<<dim3(KVDIM / 32, MROWS / 32), dim3(32, 8)>>>(v, vt, MROWS, KVDIM);

    // RoPE on Q and K (outputs tf32-rounded)
    rope_kernel<<<(MROWS * NHEADS * 64) / 256, 256>>>(q, fc, fs, NHEADS);
    rope_kernel<<<(MROWS * NKV * 64) / 256, 256>>>(k, fc, fs, NKV);

    // Causal flash attention (ctx written tf32-rounded)
    attn_kernel<<<dim3(SEQLEN / 64, NHEADS, BSZ), 128, ATTN_SMEM>>>(q, k, vt, ctx);

    // Output projection
    gemm_tf32_kernel<<<dim3(DIM / 128, MROWS / 128), 256, GEMM_SMEM>>>(
        ctx, wot, out, MROWS, DIM, DIM, DIM, DIM, DIM, 0);
}

// round 9
// speedup vs baseline: 1.8122x; 1.0573x over previous
#include <cuda_runtime.h>
#include <cuda_bf16.h>
#include <cstdint>

// Problem constants
#define BSZ      2
#define SEQLEN   2048
#define DIM      4096
#define NHEADS   32
#define NKV      8
#define HD       128
#define MROWS    (BSZ*SEQLEN)          // 4096
#define KVDIM    (NKV*HD)              // 1024

// Scratch (device globals: allocation-free rule)
__device__ float g_q[MROWS * DIM];
__device__ float g_k[MROWS * KVDIM];
__device__ float g_v[MROWS * KVDIM];
__device__ float g_vt[KVDIM * MROWS];        // V^T: [d_global][token], tf32-rounded
__device__ float g_ctx[MROWS * DIM];
// tf32-pre-rounded A operand + transposed tf32 weights ([N,K] K-major)
__device__ float g_xt[MROWS * DIM];
__device__ float g_wqt[DIM * DIM];
__device__ float g_wkt[DIM * KVDIM];
__device__ float g_wvt[DIM * KVDIM];
__device__ float g_wot[DIM * DIM];

// ---------------------------------------------------------------------------
// helpers
// ---------------------------------------------------------------------------
__device__ __forceinline__ float f2tf32(float x) {
    float y;
    asm("cvt.rna.tf32.f32 %0, %1;" : "=f"(y) : "f"(x));
    return y;
}

__device__ __forceinline__ void mma_tf32(float d[4], const uint32_t a[4],
                                         const uint32_t b[2], const float c[4]) {
    asm volatile(
        "mma.sync.aligned.m16n8k8.row.col.f32.tf32.tf32.f32 "
        "{%0,%1,%2,%3}, {%4,%5,%6,%7}, {%8,%9}, {%10,%11,%12,%13};\n"
        : "=f"(d[0]), "=f"(d[1]), "=f"(d[2]), "=f"(d[3])
        : "r"(a[0]), "r"(a[1]), "r"(a[2]), "r"(a[3]),
          "r"(b[0]), "r"(b[1]),
          "f"(c[0]), "f"(c[1]), "f"(c[2]), "f"(c[3]));
}

__device__ __forceinline__ void ldsm_x4(uint32_t d[4], uint32_t addr) {
    asm volatile(
        "ldmatrix.sync.aligned.m8n8.x4.shared.b16 {%0,%1,%2,%3}, [%4];"
        : "=r"(d[0]), "=r"(d[1]), "=r"(d[2]), "=r"(d[3]) : "r"(addr));
}

__device__ __forceinline__ void cp_async16(void* smem, const void* gmem) {
    uint32_t s = (uint32_t)__cvta_generic_to_shared(smem);
    asm volatile("cp.async.cg.shared.global [%0], [%1], 16;\n" :: "r"(s), "l"(gmem));
}
__device__ __forceinline__ void cp_commit() {
    asm volatile("cp.async.commit_group;\n" ::: "memory");
}
template<int N> __device__ __forceinline__ void cp_wait() {
    asm volatile("cp.async.wait_group %0;\n" :: "n"(N) : "memory");
}

// ---------------------------------------------------------------------------
// Elementwise tf32 pre-rounding (x)
// ---------------------------------------------------------------------------
__global__ void cvt_tf32_kernel(const float4* __restrict__ in,
                                float4* __restrict__ out, int n4)
{
    int i = blockIdx.x * blockDim.x + threadIdx.x;
    if (i < n4) {
        float4 v = in[i];
        v.x = f2tf32(v.x); v.y = f2tf32(v.y); v.z = f2tf32(v.z); v.w = f2tf32(v.w);
        out[i] = v;
    }
}

// ---------------------------------------------------------------------------
// Fused transpose + tf32 round: in[K,N] -> out[N,K]
// ---------------------------------------------------------------------------
__global__ void transpose_cvt_kernel(const float* __restrict__ in,
                                     float* __restrict__ out, int K, int N)
{
    __shared__ float t[32][33];
    int k0 = blockIdx.y * 32, n0 = blockIdx.x * 32;
    int tx = threadIdx.x, ty = threadIdx.y;
#pragma unroll
    for (int i = 0; i < 4; i++)
        t[ty + 8 * i][tx] = in[(size_t)(k0 + ty + 8 * i) * N + n0 + tx];
    __syncthreads();
#pragma unroll
    for (int i = 0; i < 4; i++)
        out[(size_t)(n0 + ty + 8 * i) * K + k0 + tx] = f2tf32(t[tx][ty + 8 * i]);
}

// ---------------------------------------------------------------------------
// TF32 GEMM v3 (unchanged from R6): C[M,N] = A[M,K] @ Bt[N,K]^T
// ---------------------------------------------------------------------------
#define GSTR 36
#define GSTRB (GSTR*4)
#define TILE_FL (128 * GSTR)
#define STG_FL (2 * TILE_FL)
#define NSTG 3
#define GEMM_SMEM (NSTG * STG_FL * 4)

__global__ __launch_bounds__(256, 2) void gemm_tf32_kernel(
    const float* __restrict__ A, const float* __restrict__ Bt,
    float* __restrict__ C, int M, int N, int K,
    int lda, int ldb, int ldc, int roundOut)
{
    extern __shared__ float sm[];
    const uint32_t sm_u32 = (uint32_t)__cvta_generic_to_shared(sm);

    const int tid  = threadIdx.x;
    const int lane = tid & 31, warp = tid >> 5;
    const int g = lane >> 2, t4 = lane & 3;
    const int wm = warp >> 1, wn = warp & 1;
    const int bm = blockIdx.y * 128, bn = blockIdx.x * 128;

    const int lm = lane >> 3, rr = lane & 7;
    const uint32_t aoff = (uint32_t)((wm * 32 + (lm & 1) * 8 + rr) * GSTRB + (lm >> 1) * 16);
    const uint32_t boff = (uint32_t)((wn * 64 + (lm >> 1) * 8 + rr) * GSTRB + (lm & 1) * 16);

    const int lrow = tid >> 3, lchk = tid & 7;
    const int ktiles = K / 32;

    float acc[2][8][4];
#pragma unroll
    for (int mi = 0; mi < 2; mi++)
#pragma unroll
        for (int ni = 0; ni < 8; ni++)
#pragma unroll
            for (int e = 0; e < 4; e++) acc[mi][ni][e] = 0.f;

    auto issue = [&](int stg, int t) {
        if (t < ktiles) {
            float* As = sm + stg * STG_FL;
            float* Bs = As + TILE_FL;
            const int kc = t * 32 + lchk * 4;
#pragma unroll
            for (int p = 0; p < 4; p++) {
                int row = lrow + p * 32;
                cp_async16(&As[row * GSTR + lchk * 4],
                           &A[(size_t)(bm + row) * lda + kc]);
                cp_async16(&Bs[row * GSTR + lchk * 4],
                           &Bt[(size_t)(bn + row) * ldb + kc]);
            }
        }
        cp_commit();
    };

    issue(0, 0);
    issue(1, 1);

    for (int t = 0; t < ktiles; t++) {
        cp_wait<1>();
        __syncthreads();
        issue((t + 2) % NSTG, t + 2);

        const uint32_t aBase = sm_u32 + (uint32_t)((t % NSTG) * STG_FL * 4) + aoff;
        const uint32_t bBase = aBase - aoff + (uint32_t)(TILE_FL * 4) + boff;

#pragma unroll
        for (int ks = 0; ks < 4; ks++) {
            uint32_t a[2][4], b[4][4];
#pragma unroll
            for (int mi = 0; mi < 2; mi++)
                ldsm_x4(a[mi], aBase + mi * 16 * GSTRB + ks * 32);
#pragma unroll
            for (int p = 0; p < 4; p++)
                ldsm_x4(b[p], bBase + p * 16 * GSTRB + ks * 32);
#pragma unroll
            for (int mi = 0; mi < 2; mi++)
#pragma unroll
                for (int ni = 0; ni < 8; ni++)
                    mma_tf32(acc[mi][ni], a[mi], &b[ni >> 1][(ni & 1) * 2], acc[mi][ni]);
        }
    }

#pragma unroll
    for (int mi = 0; mi < 2; mi++)
#pragma unroll
        for (int ni = 0; ni < 8; ni++) {
            float v0 = acc[mi][ni][0], v1 = acc[mi][ni][1];
            float v2 = acc[mi][ni][2], v3 = acc[mi][ni][3];
            if (roundOut) {
                v0 = f2tf32(v0); v1 = f2tf32(v1);
                v2 = f2tf32(v2); v3 = f2tf32(v3);
            }
            int r0 = bm + wm * 32 + mi * 16 + g;
            int cc = bn + wn * 64 + ni * 8 + t4 * 2;
            *reinterpret_cast<float2*>(&C[(size_t)r0 * ldc + cc]) = make_float2(v0, v1);
            *reinterpret_cast<float2*>(&C[(size_t)(r0 + 8) * ldc + cc]) = make_float2(v2, v3);
        }
}

// ---------------------------------------------------------------------------
// RoPE (interleaved pairs), in-place; output tf32-rounded.
// ---------------------------------------------------------------------------
__global__ void rope_kernel(float* __restrict__ t, const float* __restrict__ fc,
                            const float* __restrict__ fs, int nheads)
{
    int idx = blockIdx.x * blockDim.x + threadIdx.x;
    int fi = idx & 63;
    int hp = idx >> 6;
    int head = hp % nheads;
    int row = hp / nheads;
    int s = row & (SEQLEN - 1);
    float c = fc[s * 64 + fi], sn = fs[s * 64 + fi];
    float2* p = reinterpret_cast<float2*>(
        &t[(size_t)row * (nheads * HD) + head * HD + fi * 2]);
    float2 v = *p;
    *p = make_float2(f2tf32(v.x * c - v.y * sn), f2tf32(v.x * sn + v.y * c));
}

// ---------------------------------------------------------------------------
// Flash attention v3 (causal, GQA): 128 q-rows/CTA, 256 threads (8 warps,
// 2/SMSP), Q resident in registers, full-ldmatrix fragments, 64-key j-tiles.
// K smem [key][d]; V^T smem [d][key]; P staged through the Q staging buffer.
// ---------------------------------------------------------------------------
#define ATS2 132                  // K/P smem row stride (132 mod 32 = 4)
#define KT_FL (64 * ATS2)         // 8448 floats (K tile)
#define VT_STR 68                 // V^T smem row stride (68 mod 32 = 4)
#define VT_FL (128 * VT_STR)      // 8704 floats (V^T tile)
#define P_FL (128 * ATS2)         // 16896 floats (Q staging / P tile)
#define ATTN_SMEM ((2 * KT_FL + 2 * VT_FL + P_FL) * 4)   // 204800 B

__global__ __launch_bounds__(256) void attn_kernel(
    const float* __restrict__ Q, const float* __restrict__ Kg,
    const float* __restrict__ Vt, float* __restrict__ ctx)
{
    extern __shared__ float sm[];
    float* Ksb[2] = { sm, sm + KT_FL };
    float* Vsb[2] = { sm + 2 * KT_FL, sm + 2 * KT_FL + VT_FL };
    float* Ps     = sm + 2 * KT_FL + 2 * VT_FL;
    const uint32_t sm_u32 = (uint32_t)__cvta_generic_to_shared(sm);
    const uint32_t ks_u[2] = { sm_u32, sm_u32 + KT_FL * 4 };
    const uint32_t vs_u[2] = { sm_u32 + 2 * KT_FL * 4, sm_u32 + (2 * KT_FL + VT_FL) * 4 };
    const uint32_t ps_u = sm_u32 + (2 * KT_FL + 2 * VT_FL) * 4;

    const int qt = blockIdx.x, h = blockIdx.y, b = blockIdx.z;
    const int hkv = h >> 2;
    const int tid = threadIdx.x, lane = tid & 31, warp = tid >> 5;   // warp 0..7
    const int g = lane >> 2, t4 = lane & 3;
    const int lm = lane >> 3, rr = lane & 7;

    // ldmatrix fixed offsets (bytes)
    const uint32_t aoff = (uint32_t)((warp * 16 + (lm & 1) * 8 + rr) * ATS2 * 4 + (lm >> 1) * 16);
    const uint32_t koff = (uint32_t)(((lm >> 1) * 8 + rr) * ATS2 * 4 + (lm & 1) * 16);
    const uint32_t voff = (uint32_t)(((lm >> 1) * 8 + rr) * VT_STR * 4 + (lm & 1) * 16);

    const int lr = tid >> 5;          // 0..7
    const int lc = lane * 4;          // 0..124

    // Stage Q (128 x 128, tf32-rounded by rope) into Ps, then pull into regs
#pragma unroll
    for (int p = 0; p < 16; p++) {
        int r = lr + p * 8;
        int gr = b * SEQLEN + qt * 128 + r;
        *reinterpret_cast<float4*>(&Ps[r * ATS2 + lc]) =
            *reinterpret_cast<const float4*>(&Q[(size_t)gr * DIM + h * HD + lc]);
    }
    __syncthreads();
    uint32_t qf[16][4];
#pragma unroll
    for (int ks = 0; ks < 16; ks++)
        ldsm_x4(qf[ks], ps_u + aoff + ks * 32);

    auto issue_kv = [&](int buf, int j) {
        float* Ks = Ksb[buf];
        float* Vs = Vsb[buf];
#pragma unroll
        for (int p = 0; p < 8; p++) {
            int r = lr + p * 8;
            int gr = b * SEQLEN + j * 64 + r;
            cp_async16(&Ks[r * ATS2 + lc], &Kg[(size_t)gr * KVDIM + hkv * HD + lc]);
        }
        const int vrow = tid >> 1, vc0 = (tid & 1) * 32;
        const float* vsrc = &Vt[(size_t)(hkv * HD + vrow) * MROWS + b * SEQLEN + j * 64 + vc0];
#pragma unroll
        for (int c = 0; c < 8; c++)
            cp_async16(&Vs[vrow * VT_STR + vc0 + c * 4], vsrc + c * 4);
        cp_commit();
    };

    float m_s[2] = {-1e30f, -1e30f};
    float l_s[2] = {0.f, 0.f};
    float o[16][4];
#pragma unroll
    for (int di = 0; di < 16; di++)
#pragma unroll
        for (int e = 0; e < 4; e++) o[di][e] = 0.f;

    const float scale = 0.08838834764831845f;
    const int rowbase = qt * 128 + warp * 16;
    const int jmax = 2 * qt + 1;

    issue_kv(0, 0);

    for (int j = 0; j <= jmax; j++) {
        cp_wait<0>();
        __syncthreads();
        if (j + 1 <= jmax) issue_kv((j + 1) & 1, j + 1);

        const bool skip = (j * 64) > rowbase + 15;   // warp tile fully masked
        if (!skip) {
            const uint32_t kb = ks_u[j & 1] + koff;
            const uint32_t vb = vs_u[j & 1] + voff;

            // S = Q @ K^T : 16 k-steps (d), 8 n-tiles (64 keys)
            float s[8][4];
#pragma unroll
            for (int ni = 0; ni < 8; ni++)
#pragma unroll
                for (int e = 0; e < 4; e++) s[ni][e] = 0.f;

#pragma unroll
            for (int ks = 0; ks < 16; ks++) {
                uint32_t kf[4][4];
#pragma unroll
                for (int p = 0; p < 4; p++)
                    ldsm_x4(kf[p], kb + p * 16 * ATS2 * 4 + ks * 32);
#pragma unroll
                for (int ni = 0; ni < 8; ni++)
                    mma_tf32(s[ni], qf[ks], &kf[ni >> 1][(ni & 1) * 2], s[ni]);
            }

            // scale + causal mask (only tiles crossing the diagonal)
#pragma unroll
            for (int ni = 0; ni < 8; ni++)
#pragma unroll
                for (int e = 0; e < 4; e++) s[ni][e] *= scale;
            if (j * 64 + 63 > rowbase) {
#pragma unroll
                for (int ni = 0; ni < 8; ni++)
#pragma unroll
                    for (int e = 0; e < 4; e++) {
                        int qr = rowbase + g + (e >> 1) * 8;
                        int kc = j * 64 + ni * 8 + t4 * 2 + (e & 1);
                        if (kc > qr) s[ni][e] = -1e30f;
                    }
            }

            // online softmax (thread rows g, g+8 of warp tile)
#pragma unroll
            for (int rw = 0; rw < 2; rw++) {
                float mx = -1e30f;
#pragma unroll
                for (int ni = 0; ni < 8; ni++)
                    mx = fmaxf(mx, fmaxf(s[ni][rw * 2], s[ni][rw * 2 + 1]));
                mx = fmaxf(mx, __shfl_xor_sync(0xffffffffu, mx, 1));
                mx = fmaxf(mx, __shfl_xor_sync(0xffffffffu, mx, 2));
                float nm = fmaxf(m_s[rw], mx);
                float alpha = __expf(m_s[rw] - nm);
                m_s[rw] = nm;
                float rsum = 0.f;
#pragma unroll
                for (int ni = 0; ni < 8; ni++) {
#pragma unroll
                    for (int cc = 0; cc < 2; cc++) {
                        float pv = __expf(s[ni][rw * 2 + cc] - nm);
                        s[ni][rw * 2 + cc] = pv;
                        rsum += pv;
                    }
                }
                rsum += __shfl_xor_sync(0xffffffffu, rsum, 1);
                rsum += __shfl_xor_sync(0xffffffffu, rsum, 2);
                l_s[rw] = l_s[rw] * alpha + rsum;
#pragma unroll
                for (int di = 0; di < 16; di++) {
                    o[di][rw * 2] *= alpha;
                    o[di][rw * 2 + 1] *= alpha;
                }
            }

            __syncwarp();
            // stage P (tf32) in smem, warp-private rows (also Q staging rows of
            // this same warp — no cross-warp hazard)
#pragma unroll
            for (int ni = 0; ni < 8; ni++)
#pragma unroll
                for (int e = 0; e < 4; e++) {
                    int pr = warp * 16 + g + (e >> 1) * 8;
                    int pc = ni * 8 + t4 * 2 + (e & 1);
                    Ps[pr * ATS2 + pc] = f2tf32(s[ni][e]);
                }
            __syncwarp();

            // O += P @ V : 8 k-steps (keys), 16 n-tiles (128 d)
            const uint32_t pb = ps_u + aoff;
#pragma unroll
            for (int ks = 0; ks < 8; ks++) {
                uint32_t a[4], vf[8][4];
                ldsm_x4(a, pb + ks * 32);
#pragma unroll
                for (int p = 0; p < 8; p++)
                    ldsm_x4(vf[p], vb + p * 16 * VT_STR * 4 + ks * 32);
#pragma unroll
                for (int di = 0; di < 16; di++)
                    mma_tf32(o[di], a, &vf[di >> 1][(di & 1) * 2], o[di]);
            }
        }
    }

    // normalize + tf32-round + write ctx [row][h*128+d]
#pragma unroll
    for (int rw = 0; rw < 2; rw++) {
        float inv = 1.0f / l_s[rw];
        int gr = b * SEQLEN + rowbase + g + rw * 8;
#pragma unroll
        for (int di = 0; di < 16; di++) {
            float2 v = make_float2(f2tf32(o[di][rw * 2] * inv),
                                   f2tf32(o[di][rw * 2 + 1] * inv));
            *reinterpret_cast<float2*>(
                &ctx[(size_t)gr * DIM + h * HD + di * 8 + t4 * 2]) = v;
        }
    }
}

// ---------------------------------------------------------------------------
// launch
// ---------------------------------------------------------------------------
extern "C" void kernel_launch(void* const* d_in, const int* in_sizes, int n_in,
                              void* d_out, int out_size)
{
    const float* x  = (const float*)d_in[0];
    const float* wq = (const float*)d_in[1];
    const float* wk = (const float*)d_in[2];
    const float* wv = (const float*)d_in[3];
    const float* wo = (const float*)d_in[4];
    const float* fc = (const float*)d_in[5];
    const float* fs = (const float*)d_in[6];
    // d_in[7] = mask (causal, applied analytically), d_in[8] = start_pos (0)
    float* out = (float*)d_out;

    float *q, *k, *v, *vt, *ctx, *xt, *wqt, *wkt, *wvt, *wot;
    cudaGetSymbolAddress((void**)&q,   g_q);
    cudaGetSymbolAddress((void**)&k,   g_k);
    cudaGetSymbolAddress((void**)&v,   g_v);
    cudaGetSymbolAddress((void**)&vt,  g_vt);
    cudaGetSymbolAddress((void**)&ctx, g_ctx);
    cudaGetSymbolAddress((void**)&xt,  g_xt);
    cudaGetSymbolAddress((void**)&wqt, g_wqt);
    cudaGetSymbolAddress((void**)&wkt, g_wkt);
    cudaGetSymbolAddress((void**)&wvt, g_wvt);
    cudaGetSymbolAddress((void**)&wot, g_wot);

    cudaFuncSetAttribute(gemm_tf32_kernel,
                         cudaFuncAttributeMaxDynamicSharedMemorySize, GEMM_SMEM);
    cudaFuncSetAttribute(attn_kernel,
                         cudaFuncAttributeMaxDynamicSharedMemorySize, ATTN_SMEM);

    // A-operand rounding (x) + fused transpose+round of weights -> [N,K]
    int n4_big = MROWS * DIM / 4;
    cvt_tf32_kernel<<<(n4_big + 255) / 256, 256>>>((const float4*)x, (float4*)xt, n4_big);
    transpose_cvt_kernel<<<dim3(DIM / 32,   DIM / 32), dim3(32, 8)>>>(wq, wqt, DIM, DIM);
    transpose_cvt_kernel<<<dim3(KVDIM / 32, DIM / 32), dim3(32, 8)>>>(wk, wkt, DIM, KVDIM);
    transpose_cvt_kernel<<<dim3(KVDIM / 32, DIM / 32), dim3(32, 8)>>>(wv, wvt, DIM, KVDIM);
    transpose_cvt_kernel<<<dim3(DIM / 32,   DIM / 32), dim3(32, 8)>>>(wo, wot, DIM, DIM);

    // QKV projections
    gemm_tf32_kernel<<<dim3(DIM / 128,   MROWS / 128), 256, GEMM_SMEM>>>(
        xt, wqt, q, MROWS, DIM,   DIM, DIM, DIM, DIM,   0);
    gemm_tf32_kernel<<<dim3(KVDIM / 128, MROWS / 128), 256, GEMM_SMEM>>>(
        xt, wkt, k, MROWS, KVDIM, DIM, DIM, DIM, KVDIM, 0);
    gemm_tf32_kernel<<<dim3(KVDIM / 128, MROWS / 128), 256, GEMM_SMEM>>>(
        xt, wvt, v, MROWS, KVDIM, DIM, DIM, DIM, KVDIM, 0);

    // V^T for ldmatrix B-fragments in attention (rounding applied here)
    transpose_cvt_kernel<<<dim3(KVDIM / 32, MROWS / 32), dim3(32, 8)>>>(v, vt, MROWS, KVDIM);

    // RoPE on Q and K (outputs tf32-rounded)
    rope_kernel<<<(MROWS * NHEADS * 64) / 256, 256>>>(q, fc, fs, NHEADS);
    rope_kernel<<<(MROWS * NKV * 64) / 256, 256>>>(k, fc, fs, NKV);

    // Causal flash attention (ctx written tf32-rounded)
    attn_kernel<<<dim3(SEQLEN / 128, NHEADS, BSZ), 256, ATTN_SMEM>>>(q, k, vt, ctx);

    // Output projection
    gemm_tf32_kernel<<<dim3(DIM / 128, MROWS / 128), 256, GEMM_SMEM>>>(
        ctx, wot, out, MROWS, DIM, DIM, DIM, DIM, DIM, 0);
}

// round 10
// speedup vs baseline: 1.8848x; 1.0400x over previous
#include <cuda_runtime.h>
#include <cuda_bf16.h>
#include <cstdint>

// Problem constants
#define BSZ      2
#define SEQLEN   2048
#define DIM      4096
#define NHEADS   32
#define NKV      8
#define HD       128
#define MROWS    (BSZ*SEQLEN)          // 4096
#define KVDIM    (NKV*HD)              // 1024

// Scratch (device globals: allocation-free rule)
__device__ float g_q[MROWS * DIM];
__device__ float g_k[MROWS * KVDIM];
__device__ float g_v[MROWS * KVDIM];
__device__ float g_vt[KVDIM * MROWS];        // V^T: [d_global][token], tf32-rounded
__device__ float g_ctx[MROWS * DIM];
// tf32-pre-rounded A operand + transposed tf32 weights ([N,K] K-major)
__device__ float g_xt[MROWS * DIM];
__device__ float g_wqt[DIM * DIM];
__device__ float g_wkt[DIM * KVDIM];
__device__ float g_wvt[DIM * KVDIM];
__device__ float g_wot[DIM * DIM];

// ---------------------------------------------------------------------------
// helpers
// ---------------------------------------------------------------------------
__device__ __forceinline__ float f2tf32(float x) {
    float y;
    asm("cvt.rna.tf32.f32 %0, %1;" : "=f"(y) : "f"(x));
    return y;
}

__device__ __forceinline__ void mma_tf32(float d[4], const uint32_t a[4],
                                         const uint32_t b[2], const float c[4]) {
    asm volatile(
        "mma.sync.aligned.m16n8k8.row.col.f32.tf32.tf32.f32 "
        "{%0,%1,%2,%3}, {%4,%5,%6,%7}, {%8,%9}, {%10,%11,%12,%13};\n"
        : "=f"(d[0]), "=f"(d[1]), "=f"(d[2]), "=f"(d[3])
        : "r"(a[0]), "r"(a[1]), "r"(a[2]), "r"(a[3]),
          "r"(b[0]), "r"(b[1]),
          "f"(c[0]), "f"(c[1]), "f"(c[2]), "f"(c[3]));
}

__device__ __forceinline__ void ldsm_x4(uint32_t d[4], uint32_t addr) {
    asm volatile(
        "ldmatrix.sync.aligned.m8n8.x4.shared.b16 {%0,%1,%2,%3}, [%4];"
        : "=r"(d[0]), "=r"(d[1]), "=r"(d[2]), "=r"(d[3]) : "r"(addr));
}

__device__ __forceinline__ void cp_async16(void* smem, const void* gmem) {
    uint32_t s = (uint32_t)__cvta_generic_to_shared(smem);
    asm volatile("cp.async.cg.shared.global [%0], [%1], 16;\n" :: "r"(s), "l"(gmem));
}
__device__ __forceinline__ void cp_commit() {
    asm volatile("cp.async.commit_group;\n" ::: "memory");
}
template<int N> __device__ __forceinline__ void cp_wait() {
    asm volatile("cp.async.wait_group %0;\n" :: "n"(N) : "memory");
}

// ---------------------------------------------------------------------------
// Elementwise tf32 pre-rounding (x)
// ---------------------------------------------------------------------------
__global__ void cvt_tf32_kernel(const float4* __restrict__ in,
                                float4* __restrict__ out, int n4)
{
    int i = blockIdx.x * blockDim.x + threadIdx.x;
    if (i < n4) {
        float4 v = in[i];
        v.x = f2tf32(v.x); v.y = f2tf32(v.y); v.z = f2tf32(v.z); v.w = f2tf32(v.w);
        out[i] = v;
    }
}

// ---------------------------------------------------------------------------
// Fused transpose + tf32 round: in[K,N] -> out[N,K]
// ---------------------------------------------------------------------------
__global__ void transpose_cvt_kernel(const float* __restrict__ in,
                                     float* __restrict__ out, int K, int N)
{
    __shared__ float t[32][33];
    int k0 = blockIdx.y * 32, n0 = blockIdx.x * 32;
    int tx = threadIdx.x, ty = threadIdx.y;
#pragma unroll
    for (int i = 0; i < 4; i++)
        t[ty + 8 * i][tx] = in[(size_t)(k0 + ty + 8 * i) * N + n0 + tx];
    __syncthreads();
#pragma unroll
    for (int i = 0; i < 4; i++)
        out[(size_t)(n0 + ty + 8 * i) * K + k0 + tx] = f2tf32(t[tx][ty + 8 * i]);
}

// ---------------------------------------------------------------------------
// TF32 GEMM v4: C[M,N] = A[M,K] @ Bt[N,K]^T  (K-major, pre-rounded operands).
// blockIdx.z selects (Bt0,C0) or (Bt1,C1) — lets two same-shape GEMMs that
// individually underfill the chip run as ONE machine-filling launch.
// ---------------------------------------------------------------------------
#define GSTR 36
#define GSTRB (GSTR*4)
#define TILE_FL (128 * GSTR)
#define STG_FL (2 * TILE_FL)
#define NSTG 3
#define GEMM_SMEM (NSTG * STG_FL * 4)

__global__ __launch_bounds__(256, 2) void gemm_tf32_kernel(
    const float* __restrict__ A,
    const float* __restrict__ Bt0, const float* __restrict__ Bt1,
    float* __restrict__ C0, float* __restrict__ C1,
    int M, int N, int K, int lda, int ldb, int ldc, int roundOut)
{
    extern __shared__ float sm[];
    const uint32_t sm_u32 = (uint32_t)__cvta_generic_to_shared(sm);

    const float* __restrict__ Bt = blockIdx.z ? Bt1 : Bt0;
    float* __restrict__ C = blockIdx.z ? C1 : C0;

    const int tid  = threadIdx.x;
    const int lane = tid & 31, warp = tid >> 5;
    const int g = lane >> 2, t4 = lane & 3;
    const int wm = warp >> 1, wn = warp & 1;
    const int bm = blockIdx.y * 128, bn = blockIdx.x * 128;

    const int lm = lane >> 3, rr = lane & 7;
    const uint32_t aoff = (uint32_t)((wm * 32 + (lm & 1) * 8 + rr) * GSTRB + (lm >> 1) * 16);
    const uint32_t boff = (uint32_t)((wn * 64 + (lm >> 1) * 8 + rr) * GSTRB + (lm & 1) * 16);

    const int lrow = tid >> 3, lchk = tid & 7;
    const int ktiles = K / 32;

    float acc[2][8][4];
#pragma unroll
    for (int mi = 0; mi < 2; mi++)
#pragma unroll
        for (int ni = 0; ni < 8; ni++)
#pragma unroll
            for (int e = 0; e < 4; e++) acc[mi][ni][e] = 0.f;

    auto issue = [&](int stg, int t) {
        if (t < ktiles) {
            float* As = sm + stg * STG_FL;
            float* Bs = As + TILE_FL;
            const int kc = t * 32 + lchk * 4;
#pragma unroll
            for (int p = 0; p < 4; p++) {
                int row = lrow + p * 32;
                cp_async16(&As[row * GSTR + lchk * 4],
                           &A[(size_t)(bm + row) * lda + kc]);
                cp_async16(&Bs[row * GSTR + lchk * 4],
                           &Bt[(size_t)(bn + row) * ldb + kc]);
            }
        }
        cp_commit();
    };

    issue(0, 0);
    issue(1, 1);

    for (int t = 0; t < ktiles; t++) {
        cp_wait<1>();
        __syncthreads();
        issue((t + 2) % NSTG, t + 2);

        const uint32_t aBase = sm_u32 + (uint32_t)((t % NSTG) * STG_FL * 4) + aoff;
        const uint32_t bBase = aBase - aoff + (uint32_t)(TILE_FL * 4) + boff;

#pragma unroll
        for (int ks = 0; ks < 4; ks++) {
            uint32_t a[2][4], b[4][4];
#pragma unroll
            for (int mi = 0; mi < 2; mi++)
                ldsm_x4(a[mi], aBase + mi * 16 * GSTRB + ks * 32);
#pragma unroll
            for (int p = 0; p < 4; p++)
                ldsm_x4(b[p], bBase + p * 16 * GSTRB + ks * 32);
#pragma unroll
            for (int mi = 0; mi < 2; mi++)
#pragma unroll
                for (int ni = 0; ni < 8; ni++)
                    mma_tf32(acc[mi][ni], a[mi], &b[ni >> 1][(ni & 1) * 2], acc[mi][ni]);
        }
    }

#pragma unroll
    for (int mi = 0; mi < 2; mi++)
#pragma unroll
        for (int ni = 0; ni < 8; ni++) {
            float v0 = acc[mi][ni][0], v1 = acc[mi][ni][1];
            float v2 = acc[mi][ni][2], v3 = acc[mi][ni][3];
            if (roundOut) {
                v0 = f2tf32(v0); v1 = f2tf32(v1);
                v2 = f2tf32(v2); v3 = f2tf32(v3);
            }
            int r0 = bm + wm * 32 + mi * 16 + g;
            int cc = bn + wn * 64 + ni * 8 + t4 * 2;
            *reinterpret_cast<float2*>(&C[(size_t)r0 * ldc + cc]) = make_float2(v0, v1);
            *reinterpret_cast<float2*>(&C[(size_t)(r0 + 8) * ldc + cc]) = make_float2(v2, v3);
        }
}

// ---------------------------------------------------------------------------
// RoPE (interleaved pairs), in-place; output tf32-rounded.
// ---------------------------------------------------------------------------
__global__ void rope_kernel(float* __restrict__ t, const float* __restrict__ fc,
                            const float* __restrict__ fs, int nheads)
{
    int idx = blockIdx.x * blockDim.x + threadIdx.x;
    int fi = idx & 63;
    int hp = idx >> 6;
    int head = hp % nheads;
    int row = hp / nheads;
    int s = row & (SEQLEN - 1);
    float c = fc[s * 64 + fi], sn = fs[s * 64 + fi];
    float2* p = reinterpret_cast<float2*>(
        &t[(size_t)row * (nheads * HD) + head * HD + fi * 2]);
    float2 v = *p;
    *p = make_float2(f2tf32(v.x * c - v.y * sn), f2tf32(v.x * sn + v.y * c));
}

// ---------------------------------------------------------------------------
// Flash attention v3b (causal, GQA): 128 q-rows/CTA, 256 threads (8 warps),
// Q in registers, full-ldmatrix fragments, 64-key j-tiles.
// Grid: (NHEADS*BSZ, SEQLEN/128); qt = last-y-first (LPT: longest CTAs launch
// first, short ones backfill the tail).
// ---------------------------------------------------------------------------
#define ATS2 132                  // K/P smem row stride (132 mod 32 = 4)
#define KT_FL (64 * ATS2)         // 8448 floats (K tile)
#define VT_STR 68                 // V^T smem row stride (68 mod 32 = 4)
#define VT_FL (128 * VT_STR)      // 8704 floats (V^T tile)
#define P_FL (128 * ATS2)         // 16896 floats (Q staging / P tile)
#define ATTN_SMEM ((2 * KT_FL + 2 * VT_FL + P_FL) * 4)   // 204800 B

__global__ __launch_bounds__(256) void attn_kernel(
    const float* __restrict__ Q, const float* __restrict__ Kg,
    const float* __restrict__ Vt, float* __restrict__ ctx)
{
    extern __shared__ float sm[];
    float* Ksb[2] = { sm, sm + KT_FL };
    float* Vsb[2] = { sm + 2 * KT_FL, sm + 2 * KT_FL + VT_FL };
    float* Ps     = sm + 2 * KT_FL + 2 * VT_FL;
    const uint32_t sm_u32 = (uint32_t)__cvta_generic_to_shared(sm);
    const uint32_t ks_u[2] = { sm_u32, sm_u32 + KT_FL * 4 };
    const uint32_t vs_u[2] = { sm_u32 + 2 * KT_FL * 4, sm_u32 + (2 * KT_FL + VT_FL) * 4 };
    const uint32_t ps_u = sm_u32 + (2 * KT_FL + 2 * VT_FL) * 4;

    const int hb = blockIdx.x;
    const int h = hb & (NHEADS - 1), b = hb >> 5;
    const int qt = (gridDim.y - 1) - blockIdx.y;          // LPT: big qt first
    const int hkv = h >> 2;
    const int tid = threadIdx.x, lane = tid & 31, warp = tid >> 5;   // warp 0..7
    const int g = lane >> 2, t4 = lane & 3;
    const int lm = lane >> 3, rr = lane & 7;

    // ldmatrix fixed offsets (bytes)
    const uint32_t aoff = (uint32_t)((warp * 16 + (lm & 1) * 8 + rr) * ATS2 * 4 + (lm >> 1) * 16);
    const uint32_t koff = (uint32_t)(((lm >> 1) * 8 + rr) * ATS2 * 4 + (lm & 1) * 16);
    const uint32_t voff = (uint32_t)(((lm >> 1) * 8 + rr) * VT_STR * 4 + (lm & 1) * 16);

    const int lr = tid >> 5;          // 0..7
    const int lc = lane * 4;          // 0..124

    // Stage Q (128 x 128, tf32-rounded by rope) into Ps, then pull into regs
#pragma unroll
    for (int p = 0; p < 16; p++) {
        int r = lr + p * 8;
        int gr = b * SEQLEN + qt * 128 + r;
        *reinterpret_cast<float4*>(&Ps[r * ATS2 + lc]) =
            *reinterpret_cast<const float4*>(&Q[(size_t)gr * DIM + h * HD + lc]);
    }
    __syncthreads();
    uint32_t qf[16][4];
#pragma unroll
    for (int ks = 0; ks < 16; ks++)
        ldsm_x4(qf[ks], ps_u + aoff + ks * 32);

    auto issue_kv = [&](int buf, int j) {
        float* Ks = Ksb[buf];
        float* Vs = Vsb[buf];
#pragma unroll
        for (int p = 0; p < 8; p++) {
            int r = lr + p * 8;
            int gr = b * SEQLEN + j * 64 + r;
            cp_async16(&Ks[r * ATS2 + lc], &Kg[(size_t)gr * KVDIM + hkv * HD + lc]);
        }
        const int vrow = tid >> 1, vc0 = (tid & 1) * 32;
        const float* vsrc = &Vt[(size_t)(hkv * HD + vrow) * MROWS + b * SEQLEN + j * 64 + vc0];
#pragma unroll
        for (int c = 0; c < 8; c++)
            cp_async16(&Vs[vrow * VT_STR + vc0 + c * 4], vsrc + c * 4);
        cp_commit();
    };

    float m_s[2] = {-1e30f, -1e30f};
    float l_s[2] = {0.f, 0.f};
    float o[16][4];
#pragma unroll
    for (int di = 0; di < 16; di++)
#pragma unroll
        for (int e = 0; e < 4; e++) o[di][e] = 0.f;

    const float scale = 0.08838834764831845f;
    const int rowbase = qt * 128 + warp * 16;
    const int jmax = 2 * qt + 1;

    issue_kv(0, 0);

    for (int j = 0; j <= jmax; j++) {
        cp_wait<0>();
        __syncthreads();
        if (j + 1 <= jmax) issue_kv((j + 1) & 1, j + 1);

        const bool skip = (j * 64) > rowbase + 15;   // warp tile fully masked
        if (!skip) {
            const uint32_t kb = ks_u[j & 1] + koff;
            const uint32_t vb = vs_u[j & 1] + voff;

            // S = Q @ K^T : 16 k-steps (d), 8 n-tiles (64 keys)
            float s[8][4];
#pragma unroll
            for (int ni = 0; ni < 8; ni++)
#pragma unroll
                for (int e = 0; e < 4; e++) s[ni][e] = 0.f;

#pragma unroll
            for (int ks = 0; ks < 16; ks++) {
                uint32_t kf[4][4];
#pragma unroll
                for (int p = 0; p < 4; p++)
                    ldsm_x4(kf[p], kb + p * 16 * ATS2 * 4 + ks * 32);
#pragma unroll
                for (int ni = 0; ni < 8; ni++)
                    mma_tf32(s[ni], qf[ks], &kf[ni >> 1][(ni & 1) * 2], s[ni]);
            }

            // scale + causal mask (only tiles crossing the diagonal)
#pragma unroll
            for (int ni = 0; ni < 8; ni++)
#pragma unroll
                for (int e = 0; e < 4; e++) s[ni][e] *= scale;
            if (j * 64 + 63 > rowbase) {
#pragma unroll
                for (int ni = 0; ni < 8; ni++)
#pragma unroll
                    for (int e = 0; e < 4; e++) {
                        int qr = rowbase + g + (e >> 1) * 8;
                        int kc = j * 64 + ni * 8 + t4 * 2 + (e & 1);
                        if (kc > qr) s[ni][e] = -1e30f;
                    }
            }

            // online softmax (thread rows g, g+8 of warp tile)
#pragma unroll
            for (int rw = 0; rw < 2; rw++) {
                float mx = -1e30f;
#pragma unroll
                for (int ni = 0; ni < 8; ni++)
                    mx = fmaxf(mx, fmaxf(s[ni][rw * 2], s[ni][rw * 2 + 1]));
                mx = fmaxf(mx, __shfl_xor_sync(0xffffffffu, mx, 1));
                mx = fmaxf(mx, __shfl_xor_sync(0xffffffffu, mx, 2));
                float nm = fmaxf(m_s[rw], mx);
                float alpha = __expf(m_s[rw] - nm);
                m_s[rw] = nm;
                float rsum = 0.f;
#pragma unroll
                for (int ni = 0; ni < 8; ni++) {
#pragma unroll
                    for (int cc = 0; cc < 2; cc++) {
                        float pv = __expf(s[ni][rw * 2 + cc] - nm);
                        s[ni][rw * 2 + cc] = pv;
                        rsum += pv;
                    }
                }
                rsum += __shfl_xor_sync(0xffffffffu, rsum, 1);
                rsum += __shfl_xor_sync(0xffffffffu, rsum, 2);
                l_s[rw] = l_s[rw] * alpha + rsum;
#pragma unroll
                for (int di = 0; di < 16; di++) {
                    o[di][rw * 2] *= alpha;
                    o[di][rw * 2 + 1] *= alpha;
                }
            }

            __syncwarp();
            // stage P (tf32) in smem, warp-private rows
#pragma unroll
            for (int ni = 0; ni < 8; ni++)
#pragma unroll
                for (int e = 0; e < 4; e++) {
                    int pr = warp * 16 + g + (e >> 1) * 8;
                    int pc = ni * 8 + t4 * 2 + (e & 1);
                    Ps[pr * ATS2 + pc] = f2tf32(s[ni][e]);
                }
            __syncwarp();

            // O += P @ V : 8 k-steps (keys), 16 n-tiles (128 d)
            const uint32_t pb = ps_u + aoff;
#pragma unroll
            for (int ks = 0; ks < 8; ks++) {
                uint32_t a[4], vf[8][4];
                ldsm_x4(a, pb + ks * 32);
#pragma unroll
                for (int p = 0; p < 8; p++)
                    ldsm_x4(vf[p], vb + p * 16 * VT_STR * 4 + ks * 32);
#pragma unroll
                for (int di = 0; di < 16; di++)
                    mma_tf32(o[di], a, &vf[di >> 1][(di & 1) * 2], o[di]);
            }
        }
    }

    // normalize + tf32-round + write ctx [row][h*128+d]
#pragma unroll
    for (int rw = 0; rw < 2; rw++) {
        float inv = 1.0f / l_s[rw];
        int gr = b * SEQLEN + rowbase + g + rw * 8;
#pragma unroll
        for (int di = 0; di < 16; di++) {
            float2 v = make_float2(f2tf32(o[di][rw * 2] * inv),
                                   f2tf32(o[di][rw * 2 + 1] * inv));
            *reinterpret_cast<float2*>(
                &ctx[(size_t)gr * DIM + h * HD + di * 8 + t4 * 2]) = v;
        }
    }
}

// ---------------------------------------------------------------------------
// launch
// ---------------------------------------------------------------------------
extern "C" void kernel_launch(void* const* d_in, const int* in_sizes, int n_in,
                              void* d_out, int out_size)
{
    const float* x  = (const float*)d_in[0];
    const float* wq = (const float*)d_in[1];
    const float* wk = (const float*)d_in[2];
    const float* wv = (const float*)d_in[3];
    const float* wo = (const float*)d_in[4];
    const float* fc = (const float*)d_in[5];
    const float* fs = (const float*)d_in[6];
    // d_in[7] = mask (causal, applied analytically), d_in[8] = start_pos (0)
    float* out = (float*)d_out;

    float *q, *k, *v, *vt, *ctx, *xt, *wqt, *wkt, *wvt, *wot;
    cudaGetSymbolAddress((void**)&q,   g_q);
    cudaGetSymbolAddress((void**)&k,   g_k);
    cudaGetSymbolAddress((void**)&v,   g_v);
    cudaGetSymbolAddress((void**)&vt,  g_vt);
    cudaGetSymbolAddress((void**)&ctx, g_ctx);
    cudaGetSymbolAddress((void**)&xt,  g_xt);
    cudaGetSymbolAddress((void**)&wqt, g_wqt);
    cudaGetSymbolAddress((void**)&wkt, g_wkt);
    cudaGetSymbolAddress((void**)&wvt, g_wvt);
    cudaGetSymbolAddress((void**)&wot, g_wot);

    cudaFuncSetAttribute(gemm_tf32_kernel,
                         cudaFuncAttributeMaxDynamicSharedMemorySize, GEMM_SMEM);
    cudaFuncSetAttribute(attn_kernel,
                         cudaFuncAttributeMaxDynamicSharedMemorySize, ATTN_SMEM);

    // A-operand rounding (x) + fused transpose+round of weights -> [N,K]
    int n4_big = MROWS * DIM / 4;
    cvt_tf32_kernel<<<(n4_big + 255) / 256, 256>>>((const float4*)x, (float4*)xt, n4_big);
    transpose_cvt_kernel<<<dim3(DIM / 32,   DIM / 32), dim3(32, 8)>>>(wq, wqt, DIM, DIM);
    transpose_cvt_kernel<<<dim3(KVDIM / 32, DIM / 32), dim3(32, 8)>>>(wk, wkt, DIM, KVDIM);
    transpose_cvt_kernel<<<dim3(KVDIM / 32, DIM / 32), dim3(32, 8)>>>(wv, wvt, DIM, KVDIM);
    transpose_cvt_kernel<<<dim3(DIM / 32,   DIM / 32), dim3(32, 8)>>>(wo, wot, DIM, DIM);

    // Q projection (full-size launch)
    gemm_tf32_kernel<<<dim3(DIM / 128, MROWS / 128, 1), 256, GEMM_SMEM>>>(
        xt, wqt, wqt, q, q, MROWS, DIM, DIM, DIM, DIM, DIM, 0);
    // K + V projections merged into ONE machine-filling launch (z selects)
    gemm_tf32_kernel<<<dim3(KVDIM / 128, MROWS / 128, 2), 256, GEMM_SMEM>>>(
        xt, wkt, wvt, k, v, MROWS, KVDIM, DIM, DIM, DIM, KVDIM, 0);

    // V^T for ldmatrix B-fragments in attention (rounding applied here)
    transpose_cvt_kernel<<<dim3(KVDIM / 32, MROWS / 32), dim3(32, 8)>>>(v, vt, MROWS, KVDIM);

    // RoPE on Q and K (outputs tf32-rounded)
    rope_kernel<<<(MROWS * NHEADS * 64) / 256, 256>>>(q, fc, fs, NHEADS);
    rope_kernel<<<(MROWS * NKV * 64) / 256, 256>>>(k, fc, fs, NKV);

    // Causal flash attention, LPT-ordered (ctx written tf32-rounded)
    attn_kernel<<<dim3(NHEADS * BSZ, SEQLEN / 128), 256, ATTN_SMEM>>>(q, k, vt, ctx);

    // Output projection
    gemm_tf32_kernel<<<dim3(DIM / 128, MROWS / 128, 1), 256, GEMM_SMEM>>>(
        ctx, wot, wot, out, out, MROWS, DIM, DIM, DIM, DIM, DIM, 0);
}

// round 12
// speedup vs baseline: 3.5603x; 1.8890x over previous
#include <cuda_runtime.h>
#include <cuda_fp16.h>
#include <cstdint>

// Problem constants
#define BSZ      2
#define SEQLEN   2048
#define DIM      4096
#define NHEADS   32
#define NKV      8
#define HD       128
#define MROWS    (BSZ*SEQLEN)          // 4096
#define KVDIM    (NKV*HD)              // 1024

// Scratch (device globals: allocation-free rule)
__device__ float  g_q[MROWS * DIM];          // fp32 GEMM outputs
__device__ float  g_k[MROWS * KVDIM];
__device__ float  g_v[MROWS * KVDIM];
__device__ __half g_qh[MROWS * DIM];         // roped, half
__device__ __half g_kh[MROWS * KVDIM];
__device__ __half g_vth[KVDIM * MROWS];      // V^T [d_global][token], half
__device__ __half g_ctxh[MROWS * DIM];       // attention output, half
__device__ __half g_xh[MROWS * DIM];         // x in half
__device__ __half g_wqh[DIM * DIM];          // transposed weights [N,K], half
__device__ __half g_wkh[DIM * KVDIM];
__device__ __half g_wvh[DIM * KVDIM];
__device__ __half g_woh[DIM * DIM];

// ---------------------------------------------------------------------------
// helpers
// ---------------------------------------------------------------------------
__device__ __forceinline__ void mma_f16(float d[4], const uint32_t a[4],
                                        const uint32_t b[2], const float c[4]) {
    asm volatile(
        "mma.sync.aligned.m16n8k16.row.col.f32.f16.f16.f32 "
        "{%0,%1,%2,%3}, {%4,%5,%6,%7}, {%8,%9}, {%10,%11,%12,%13};\n"
        : "=f"(d[0]), "=f"(d[1]), "=f"(d[2]), "=f"(d[3])
        : "r"(a[0]), "r"(a[1]), "r"(a[2]), "r"(a[3]),
          "r"(b[0]), "r"(b[1]),
          "f"(c[0]), "f"(c[1]), "f"(c[2]), "f"(c[3]));
}

__device__ __forceinline__ void ldsm_x4(uint32_t d[4], uint32_t addr) {
    asm volatile(
        "ldmatrix.sync.aligned.m8n8.x4.shared.b16 {%0,%1,%2,%3}, [%4];"
        : "=r"(d[0]), "=r"(d[1]), "=r"(d[2]), "=r"(d[3]) : "r"(addr));
}

__device__ __forceinline__ void cp_async16(void* smem, const void* gmem) {
    uint32_t s = (uint32_t)__cvta_generic_to_shared(smem);
    asm volatile("cp.async.cg.shared.global [%0], [%1], 16;\n" :: "r"(s), "l"(gmem));
}
__device__ __forceinline__ void cp_commit() {
    asm volatile("cp.async.commit_group;\n" ::: "memory");
}
template<int N> __device__ __forceinline__ void cp_wait() {
    asm volatile("cp.async.wait_group %0;\n" :: "n"(N) : "memory");
}

// ---------------------------------------------------------------------------
// fp32 -> half elementwise (x)
// ---------------------------------------------------------------------------
__global__ void cvt_h_kernel(const float4* __restrict__ in,
                             uint2* __restrict__ out, int n4)
{
    int i = blockIdx.x * blockDim.x + threadIdx.x;
    if (i < n4) {
        float4 v = in[i];
        __half2 lo = __floats2half2_rn(v.x, v.y);
        __half2 hi = __floats2half2_rn(v.z, v.w);
        uint2 o;
        o.x = *reinterpret_cast<uint32_t*>(&lo);
        o.y = *reinterpret_cast<uint32_t*>(&hi);
        out[i] = o;
    }
}

// ---------------------------------------------------------------------------
// Fused transpose + half round: in[K,N] fp32 -> out[N,K] half
// ---------------------------------------------------------------------------
__global__ void transpose_cvt_h_kernel(const float* __restrict__ in,
                                       __half* __restrict__ out, int K, int N)
{
    __shared__ float t[32][33];
    int k0 = blockIdx.y * 32, n0 = blockIdx.x * 32;
    int tx = threadIdx.x, ty = threadIdx.y;
#pragma unroll
    for (int i = 0; i < 4; i++)
        t[ty + 8 * i][tx] = in[(size_t)(k0 + ty + 8 * i) * N + n0 + tx];
    __syncthreads();
#pragma unroll
    for (int i = 0; i < 4; i++)
        out[(size_t)(n0 + ty + 8 * i) * K + k0 + tx] = __float2half_rn(t[tx][ty + 8 * i]);
}

// ---------------------------------------------------------------------------
// FP16 GEMM: C[M,N]fp32 = A[M,K]h @ Bt[N,K]h^T  (K-major). Block 128x128,
// BK=64 halfs, 256 threads (8 warps 4x2, warp tile 32x64), 3-stage cp.async,
// all fragments via ldmatrix, m16n8k16 f16 mma with fp32 accum.
// blockIdx.z selects (Bt0,C0)/(Bt1,C1) to merge same-shape GEMMs.
// ---------------------------------------------------------------------------
#define HSTR 72                       // halfs per smem row (144 B)
#define HSTRB 144
#define HTILE (128 * HSTR)            // halfs per operand tile
#define HSTG (2 * HTILE)              // halfs per stage
#define NSTG 3
#define GEMM_SMEM (NSTG * HSTG * 2)   // 110592 B -> 2 CTAs/SM

__global__ __launch_bounds__(256, 2) void gemm_f16_kernel(
    const __half* __restrict__ A,
    const __half* __restrict__ Bt0, const __half* __restrict__ Bt1,
    float* __restrict__ C0, float* __restrict__ C1,
    int M, int N, int K, int lda, int ldb, int ldc)
{
    extern __shared__ __half smh[];
    const uint32_t sm_u32 = (uint32_t)__cvta_generic_to_shared(smh);

    const __half* __restrict__ Bt = blockIdx.z ? Bt1 : Bt0;
    float* __restrict__ C = blockIdx.z ? C1 : C0;

    const int tid  = threadIdx.x;
    const int lane = tid & 31, warp = tid >> 5;
    const int g = lane >> 2, t4 = lane & 3;
    const int wm = warp >> 1, wn = warp & 1;
    const int bm = blockIdx.y * 128, bn = blockIdx.x * 128;

    const int lm = lane >> 3, rr = lane & 7;
    // A-frag: m0 rows+0/k0-7, m1 rows+8/k0-7, m2 rows+0/k8-15, m3 rows+8/k8-15
    const uint32_t aoff = (uint32_t)((wm * 32 + (lm & 1) * 8 + rr) * HSTRB + (lm >> 1) * 16);
    // B-frag x4: m0 n+0/k0-7, m1 n+0/k8-15, m2 n+8/k0-7, m3 n+8/k8-15
    const uint32_t boff = (uint32_t)((wn * 64 + (lm >> 1) * 8 + rr) * HSTRB + (lm & 1) * 16);

    const int lrow = tid >> 3, lchk = tid & 7;   // 32 rows/pass x 8x16B chunks
    const int ktiles = K / 64;

    float acc[2][8][4];
#pragma unroll
    for (int mi = 0; mi < 2; mi++)
#pragma unroll
        for (int ni = 0; ni < 8; ni++)
#pragma unroll
            for (int e = 0; e < 4; e++) acc[mi][ni][e] = 0.f;

    auto issue = [&](int stg, int t) {
        if (t < ktiles) {
            __half* As = smh + stg * HSTG;
            __half* Bs = As + HTILE;
            const int kc = t * 64 + lchk * 8;
#pragma unroll
            for (int p = 0; p < 4; p++) {
                int row = lrow + p * 32;
                cp_async16(&As[row * HSTR + lchk * 8],
                           &A[(size_t)(bm + row) * lda + kc]);
                cp_async16(&Bs[row * HSTR + lchk * 8],
                           &Bt[(size_t)(bn + row) * ldb + kc]);
            }
        }
        cp_commit();
    };

    issue(0, 0);
    issue(1, 1);

    for (int t = 0; t < ktiles; t++) {
        cp_wait<1>();
        __syncthreads();
        issue((t + 2) % NSTG, t + 2);

        const uint32_t aBase = sm_u32 + (uint32_t)((t % NSTG) * HSTG * 2) + aoff;
        const uint32_t bBase = aBase - aoff + (uint32_t)(HTILE * 2) + boff;

#pragma unroll
        for (int ks = 0; ks < 4; ks++) {           // 4 x k16
            uint32_t a[2][4], b[4][4];
#pragma unroll
            for (int mi = 0; mi < 2; mi++)
                ldsm_x4(a[mi], aBase + mi * 16 * HSTRB + ks * 32);
#pragma unroll
            for (int p = 0; p < 4; p++)
                ldsm_x4(b[p], bBase + p * 16 * HSTRB + ks * 32);
#pragma unroll
            for (int mi = 0; mi < 2; mi++)
#pragma unroll
                for (int ni = 0; ni < 8; ni++)
                    mma_f16(acc[mi][ni], a[mi], &b[ni >> 1][(ni & 1) * 2], acc[mi][ni]);
        }
    }

#pragma unroll
    for (int mi = 0; mi < 2; mi++)
#pragma unroll
        for (int ni = 0; ni < 8; ni++) {
            int r0 = bm + wm * 32 + mi * 16 + g;
            int cc = bn + wn * 64 + ni * 8 + t4 * 2;
            *reinterpret_cast<float2*>(&C[(size_t)r0 * ldc + cc]) =
                make_float2(acc[mi][ni][0], acc[mi][ni][1]);
            *reinterpret_cast<float2*>(&C[(size_t)(r0 + 8) * ldc + cc]) =
                make_float2(acc[mi][ni][2], acc[mi][ni][3]);
        }
}

// ---------------------------------------------------------------------------
// RoPE: read fp32 projection, write roped HALF buffer.
// ---------------------------------------------------------------------------
__global__ void rope_h_kernel(const float* __restrict__ in, __half* __restrict__ out,
                              const float* __restrict__ fc, const float* __restrict__ fs,
                              int nheads)
{
    int idx = blockIdx.x * blockDim.x + threadIdx.x;
    int fi = idx & 63;
    int hp = idx >> 6;
    int head = hp % nheads;
    int row = hp / nheads;
    int s = row & (SEQLEN - 1);
    float c = fc[s * 64 + fi], sn = fs[s * 64 + fi];
    size_t ofs = (size_t)row * (nheads * HD) + head * HD + fi * 2;
    float2 v = *reinterpret_cast<const float2*>(&in[ofs]);
    *reinterpret_cast<__half2*>(&out[ofs]) =
        __floats2half2_rn(v.x * c - v.y * sn, v.x * sn + v.y * c);
}

// ---------------------------------------------------------------------------
// Flash attention v4 (causal, GQA), ALL-FP16 operands, fp32 accum/softmax.
// 128 q-rows/CTA, 256 threads (8 warps), Q in regs (8x k16 frags),
// 64-key j-tiles, full-ldmatrix, LPT grid ordering.
// ---------------------------------------------------------------------------
#define KSTRH 136                 // K/Q-stage smem stride in halfs (272 B)
#define VSTRH 72                  // V^T / P smem stride in halfs (144 B)
#define KT_H (64 * KSTRH)         // 8704 halfs
#define VT_H (128 * VSTRH)        // 9216 halfs
#define PQ_H (128 * KSTRH)        // 17408 halfs (Q staging; P reuses at VSTRH)
#define ATTN_SMEM ((2 * KT_H + 2 * VT_H + PQ_H) * 2)   // 106496 B

__global__ __launch_bounds__(256) void attn_kernel(
    const __half* __restrict__ Qh, const __half* __restrict__ Kh,
    const __half* __restrict__ Vth, __half* __restrict__ ctxh)
{
    extern __shared__ __half smh[];
    __half* Ksb[2] = { smh, smh + KT_H };
    __half* Vsb[2] = { smh + 2 * KT_H, smh + 2 * KT_H + VT_H };
    __half* Ps     = smh + 2 * KT_H + 2 * VT_H;
    const uint32_t sm_u32 = (uint32_t)__cvta_generic_to_shared(smh);
    const uint32_t ks_u[2] = { sm_u32, sm_u32 + KT_H * 2 };
    const uint32_t vs_u[2] = { sm_u32 + 2 * KT_H * 2, sm_u32 + (2 * KT_H + VT_H) * 2 };
    const uint32_t ps_u = sm_u32 + (2 * KT_H + 2 * VT_H) * 2;

    const int hb = blockIdx.x;
    const int h = hb & (NHEADS - 1), b = hb >> 5;
    const int qt = (gridDim.y - 1) - blockIdx.y;          // LPT: big qt first
    const int hkv = h >> 2;
    const int tid = threadIdx.x, lane = tid & 31, warp = tid >> 5;   // 0..7
    const int g = lane >> 2, t4 = lane & 3;
    const int lm = lane >> 3, rr = lane & 7;

    // ldmatrix fixed offsets (bytes)
    const uint32_t qoff = (uint32_t)((warp * 16 + (lm & 1) * 8 + rr) * (KSTRH * 2) + (lm >> 1) * 16);
    const uint32_t poff = (uint32_t)((warp * 16 + (lm & 1) * 8 + rr) * (VSTRH * 2) + (lm >> 1) * 16);
    const uint32_t koff = (uint32_t)(((lm >> 1) * 8 + rr) * (KSTRH * 2) + (lm & 1) * 16);
    const uint32_t voff = (uint32_t)(((lm >> 1) * 8 + rr) * (VSTRH * 2) + (lm & 1) * 16);

    // Stage Q (128 x 128 halfs) into Ps (stride KSTRH), then pull into regs
    {
        const int r0 = tid >> 4, c8 = (tid & 15) * 8;
#pragma unroll
        for (int p = 0; p < 8; p++) {
            int r = r0 + p * 16;
            int gr = b * SEQLEN + qt * 128 + r;
            *reinterpret_cast<uint4*>(&Ps[r * KSTRH + c8]) =
                *reinterpret_cast<const uint4*>(&Qh[(size_t)gr * DIM + h * HD + c8]);
        }
    }
    __syncthreads();
    uint32_t qf[8][4];
#pragma unroll
    for (int ks = 0; ks < 8; ks++)
        ldsm_x4(qf[ks], ps_u + qoff + ks * 32);

    auto issue_kv = [&](int buf, int j) {
        __half* Ks = Ksb[buf];
        __half* Vs = Vsb[buf];
        const int kr0 = tid >> 4, kc8 = (tid & 15) * 8;
#pragma unroll
        for (int p = 0; p < 4; p++) {
            int r = kr0 + p * 16;
            int gr = b * SEQLEN + j * 64 + r;
            cp_async16(&Ks[r * KSTRH + kc8], &Kh[(size_t)gr * KVDIM + hkv * HD + kc8]);
        }
        const int vrow = tid >> 1, vc0 = (tid & 1) * 32;
        const __half* vsrc = &Vth[(size_t)(hkv * HD + vrow) * MROWS + b * SEQLEN + j * 64 + vc0];
#pragma unroll
        for (int c = 0; c < 4; c++)
            cp_async16(&Vs[vrow * VSTRH + vc0 + c * 8], vsrc + c * 8);
        cp_commit();
    };

    float m_s[2] = {-1e30f, -1e30f};
    float l_s[2] = {0.f, 0.f};
    float o[16][4];
#pragma unroll
    for (int di = 0; di < 16; di++)
#pragma unroll
        for (int e = 0; e < 4; e++) o[di][e] = 0.f;

    const float scale = 0.08838834764831845f;
    const int rowbase = qt * 128 + warp * 16;
    const int jmax = 2 * qt + 1;

    issue_kv(0, 0);

    for (int j = 0; j <= jmax; j++) {
        cp_wait<0>();
        __syncthreads();
        if (j + 1 <= jmax) issue_kv((j + 1) & 1, j + 1);

        const bool skip = (j * 64) > rowbase + 15;   // warp tile fully masked
        if (!skip) {
            const uint32_t kb = ks_u[j & 1] + koff;
            const uint32_t vb = vs_u[j & 1] + voff;

            // S = Q @ K^T : 8 k16-steps (d=128), 8 n-groups (64 keys)
            float s[8][4];
#pragma unroll
            for (int ni = 0; ni < 8; ni++)
#pragma unroll
                for (int e = 0; e < 4; e++) s[ni][e] = 0.f;

#pragma unroll
            for (int ks = 0; ks < 8; ks++) {
                uint32_t kf[4][4];
#pragma unroll
                for (int p = 0; p < 4; p++)
                    ldsm_x4(kf[p], kb + p * 16 * (KSTRH * 2) + ks * 32);
#pragma unroll
                for (int ni = 0; ni < 8; ni++)
                    mma_f16(s[ni], qf[ks], &kf[ni >> 1][(ni & 1) * 2], s[ni]);
            }

            // scale + causal mask (only tiles crossing the diagonal)
#pragma unroll
            for (int ni = 0; ni < 8; ni++)
#pragma unroll
                for (int e = 0; e < 4; e++) s[ni][e] *= scale;
            if (j * 64 + 63 > rowbase) {
#pragma unroll
                for (int ni = 0; ni < 8; ni++)
#pragma unroll
                    for (int e = 0; e < 4; e++) {
                        int qr = rowbase + g + (e >> 1) * 8;
                        int kc = j * 64 + ni * 8 + t4 * 2 + (e & 1);
                        if (kc > qr) s[ni][e] = -1e30f;
                    }
            }

            // online softmax (thread rows g, g+8 of warp tile), fp32
#pragma unroll
            for (int rw = 0; rw < 2; rw++) {
                float mx = -1e30f;
#pragma unroll
                for (int ni = 0; ni < 8; ni++)
                    mx = fmaxf(mx, fmaxf(s[ni][rw * 2], s[ni][rw * 2 + 1]));
                mx = fmaxf(mx, __shfl_xor_sync(0xffffffffu, mx, 1));
                mx = fmaxf(mx, __shfl_xor_sync(0xffffffffu, mx, 2));
                float nm = fmaxf(m_s[rw], mx);
                float alpha = __expf(m_s[rw] - nm);
                m_s[rw] = nm;
                float rsum = 0.f;
#pragma unroll
                for (int ni = 0; ni < 8; ni++) {
#pragma unroll
                    for (int cc = 0; cc < 2; cc++) {
                        float pv = __expf(s[ni][rw * 2 + cc] - nm);
                        s[ni][rw * 2 + cc] = pv;
                        rsum += pv;
                    }
                }
                rsum += __shfl_xor_sync(0xffffffffu, rsum, 1);
                rsum += __shfl_xor_sync(0xffffffffu, rsum, 2);
                l_s[rw] = l_s[rw] * alpha + rsum;
#pragma unroll
                for (int di = 0; di < 16; di++) {
                    o[di][rw * 2] *= alpha;
                    o[di][rw * 2 + 1] *= alpha;
                }
            }

            __syncwarp();
            // stage P as half2 pairs, warp-private rows (stride VSTRH)
#pragma unroll
            for (int ni = 0; ni < 8; ni++)
#pragma unroll
                for (int rw = 0; rw < 2; rw++) {
                    int pr = warp * 16 + g + rw * 8;
                    int pc = ni * 8 + t4 * 2;
                    *reinterpret_cast<__half2*>(&Ps[pr * VSTRH + pc]) =
                        __floats2half2_rn(s[ni][rw * 2], s[ni][rw * 2 + 1]);
                }
            __syncwarp();

            // O += P @ V : 4 k16-steps (64 keys), 16 d-groups (128 d)
#pragma unroll
            for (int ks = 0; ks < 4; ks++) {
                uint32_t a[4], vf[8][4];
                ldsm_x4(a, ps_u + poff + ks * 32);
#pragma unroll
                for (int p = 0; p < 8; p++)
                    ldsm_x4(vf[p], vb + p * 16 * (VSTRH * 2) + ks * 32);
#pragma unroll
                for (int di = 0; di < 16; di++)
                    mma_f16(o[di], a, &vf[di >> 1][(di & 1) * 2], o[di]);
            }
        }
    }

    // normalize + write ctx as half [row][h*128+d]
#pragma unroll
    for (int rw = 0; rw < 2; rw++) {
        float inv = 1.0f / l_s[rw];
        int gr = b * SEQLEN + rowbase + g + rw * 8;
#pragma unroll
        for (int di = 0; di < 16; di++) {
            *reinterpret_cast<__half2*>(
                &ctxh[(size_t)gr * DIM + h * HD + di * 8 + t4 * 2]) =
                __floats2half2_rn(o[di][rw * 2] * inv, o[di][rw * 2 + 1] * inv);
        }
    }
}

// ---------------------------------------------------------------------------
// launch
// ---------------------------------------------------------------------------
extern "C" void kernel_launch(void* const* d_in, const int* in_sizes, int n_in,
                              void* d_out, int out_size)
{
    const float* x  = (const float*)d_in[0];
    const float* wq = (const float*)d_in[1];
    const float* wk = (const float*)d_in[2];
    const float* wv = (const float*)d_in[3];
    const float* wo = (const float*)d_in[4];
    const float* fc = (const float*)d_in[5];
    const float* fs = (const float*)d_in[6];
    // d_in[7] = mask (causal, applied analytically), d_in[8] = start_pos (0)
    float* out = (float*)d_out;

    float *q, *k, *v;
    __half *qh, *kh, *vth, *ctxh, *xh, *wqh, *wkh, *wvh, *woh;
    cudaGetSymbolAddress((void**)&q,    g_q);
    cudaGetSymbolAddress((void**)&k,    g_k);
    cudaGetSymbolAddress((void**)&v,    g_v);
    cudaGetSymbolAddress((void**)&qh,   g_qh);
    cudaGetSymbolAddress((void**)&kh,   g_kh);
    cudaGetSymbolAddress((void**)&vth,  g_vth);
    cudaGetSymbolAddress((void**)&ctxh, g_ctxh);
    cudaGetSymbolAddress((void**)&xh,   g_xh);
    cudaGetSymbolAddress((void**)&wqh,  g_wqh);
    cudaGetSymbolAddress((void**)&wkh,  g_wkh);
    cudaGetSymbolAddress((void**)&wvh,  g_wvh);
    cudaGetSymbolAddress((void**)&woh,  g_woh);

    cudaFuncSetAttribute(gemm_f16_kernel,
                         cudaFuncAttributeMaxDynamicSharedMemorySize, GEMM_SMEM);
    cudaFuncSetAttribute(attn_kernel,
                         cudaFuncAttributeMaxDynamicSharedMemorySize, ATTN_SMEM);

    // x -> half, weights -> transposed half [N,K]
    int n4_big = MROWS * DIM / 4;
    cvt_h_kernel<<<(n4_big + 255) / 256, 256>>>((const float4*)x, (uint2*)xh, n4_big);
    transpose_cvt_h_kernel<<<dim3(DIM / 32,   DIM / 32), dim3(32, 8)>>>(wq, wqh, DIM, DIM);
    transpose_cvt_h_kernel<<<dim3(KVDIM / 32, DIM / 32), dim3(32, 8)>>>(wk, wkh, DIM, KVDIM);
    transpose_cvt_h_kernel<<<dim3(KVDIM / 32, DIM / 32), dim3(32, 8)>>>(wv, wvh, DIM, KVDIM);
    transpose_cvt_h_kernel<<<dim3(DIM / 32,   DIM / 32), dim3(32, 8)>>>(wo, woh, DIM, DIM);

    // Q projection; K+V merged into one machine-filling launch
    gemm_f16_kernel<<<dim3(DIM / 128, MROWS / 128, 1), 256, GEMM_SMEM>>>(
        xh, wqh, wqh, q, q, MROWS, DIM, DIM, DIM, DIM, DIM);
    gemm_f16_kernel<<<dim3(KVDIM / 128, MROWS / 128, 2), 256, GEMM_SMEM>>>(
        xh, wkh, wvh, k, v, MROWS, KVDIM, DIM, DIM, DIM, KVDIM);

    // RoPE: fp32 -> half roped buffers; V^T: fp32 -> half transposed
    rope_h_kernel<<<(MROWS * NHEADS * 64) / 256, 256>>>(q, qh, fc, fs, NHEADS);
    rope_h_kernel<<<(MROWS * NKV * 64) / 256, 256>>>(k, kh, fc, fs, NKV);
    transpose_cvt_h_kernel<<<dim3(KVDIM / 32, MROWS / 32), dim3(32, 8)>>>(v, vth, MROWS, KVDIM);

    // Causal flash attention (half in, half out), LPT-ordered
    attn_kernel<<<dim3(NHEADS * BSZ, SEQLEN / 128), 256, ATTN_SMEM>>>(qh, kh, vth, ctxh);

    // Output projection (half ctx @ half wo -> fp32 out)
    gemm_f16_kernel<<<dim3(DIM / 128, MROWS / 128, 1), 256, GEMM_SMEM>>>(
        ctxh, woh, woh, out, out, MROWS, DIM, DIM, DIM, DIM, DIM);
}

// round 13
// speedup vs baseline: 3.5764x; 1.0045x over previous
#include <cuda_runtime.h>
#include <cuda_fp16.h>
#include <cstdint>

// Problem constants
#define BSZ      2
#define SEQLEN   2048
#define DIM      4096
#define NHEADS   32
#define NKV      8
#define HD       128
#define MROWS    (BSZ*SEQLEN)          // 4096
#define KVDIM    (NKV*HD)              // 1024

// Scratch (device globals: allocation-free rule)
__device__ float  g_v[MROWS * KVDIM];        // V projection (fp32, for V^T pass)
__device__ __half g_qh[MROWS * DIM];         // roped Q, half
__device__ __half g_kh[MROWS * KVDIM];       // roped K, half
__device__ __half g_vth[KVDIM * MROWS];      // V^T [d_global][token], half
__device__ __half g_ctxh[MROWS * DIM];       // attention output, half
__device__ __half g_xh[MROWS * DIM];         // x in half
__device__ __half g_wqh[DIM * DIM];          // transposed weights [N,K], half
__device__ __half g_wkh[DIM * KVDIM];
__device__ __half g_wvh[DIM * KVDIM];
__device__ __half g_woh[DIM * DIM];

// ---------------------------------------------------------------------------
// helpers
// ---------------------------------------------------------------------------
__device__ __forceinline__ void mma_f16(float d[4], const uint32_t a[4],
                                        const uint32_t b[2], const float c[4]) {
    asm volatile(
        "mma.sync.aligned.m16n8k16.row.col.f32.f16.f16.f32 "
        "{%0,%1,%2,%3}, {%4,%5,%6,%7}, {%8,%9}, {%10,%11,%12,%13};\n"
        : "=f"(d[0]), "=f"(d[1]), "=f"(d[2]), "=f"(d[3])
        : "r"(a[0]), "r"(a[1]), "r"(a[2]), "r"(a[3]),
          "r"(b[0]), "r"(b[1]),
          "f"(c[0]), "f"(c[1]), "f"(c[2]), "f"(c[3]));
}

__device__ __forceinline__ void ldsm_x4(uint32_t d[4], uint32_t addr) {
    asm volatile(
        "ldmatrix.sync.aligned.m8n8.x4.shared.b16 {%0,%1,%2,%3}, [%4];"
        : "=r"(d[0]), "=r"(d[1]), "=r"(d[2]), "=r"(d[3]) : "r"(addr));
}

__device__ __forceinline__ void cp_async16(void* smem, const void* gmem) {
    uint32_t s = (uint32_t)__cvta_generic_to_shared(smem);
    asm volatile("cp.async.cg.shared.global [%0], [%1], 16;\n" :: "r"(s), "l"(gmem));
}
__device__ __forceinline__ void cp_commit() {
    asm volatile("cp.async.commit_group;\n" ::: "memory");
}
template<int N> __device__ __forceinline__ void cp_wait() {
    asm volatile("cp.async.wait_group %0;\n" :: "n"(N) : "memory");
}

// ---------------------------------------------------------------------------
// fp32 -> half elementwise (x)
// ---------------------------------------------------------------------------
__global__ void cvt_h_kernel(const float4* __restrict__ in,
                             uint2* __restrict__ out, int n4)
{
    int i = blockIdx.x * blockDim.x + threadIdx.x;
    if (i < n4) {
        float4 v = in[i];
        __half2 lo = __floats2half2_rn(v.x, v.y);
        __half2 hi = __floats2half2_rn(v.z, v.w);
        uint2 o;
        o.x = *reinterpret_cast<uint32_t*>(&lo);
        o.y = *reinterpret_cast<uint32_t*>(&hi);
        out[i] = o;
    }
}

// ---------------------------------------------------------------------------
// Merged weight transposes: z selects {wq, wk, wv, wo}; in[K,N]f32 -> out[N,K]h
// ---------------------------------------------------------------------------
__global__ void transpose_all_kernel(
    const float* __restrict__ wq, const float* __restrict__ wk,
    const float* __restrict__ wv, const float* __restrict__ wo,
    __half* __restrict__ wqh, __half* __restrict__ wkh,
    __half* __restrict__ wvh, __half* __restrict__ woh)
{
    const int z = blockIdx.z;
    const float* in; __half* out; int N;
    if (z == 0)      { in = wq; out = wqh; N = DIM; }
    else if (z == 1) { in = wk; out = wkh; N = KVDIM; }
    else if (z == 2) { in = wv; out = wvh; N = KVDIM; }
    else             { in = wo; out = woh; N = DIM; }
    int n0 = blockIdx.x * 32;
    if (n0 >= N) return;
    __shared__ float t[32][33];
    int k0 = blockIdx.y * 32;
    int tx = threadIdx.x, ty = threadIdx.y;
#pragma unroll
    for (int i = 0; i < 4; i++)
        t[ty + 8 * i][tx] = in[(size_t)(k0 + ty + 8 * i) * N + n0 + tx];
    __syncthreads();
#pragma unroll
    for (int i = 0; i < 4; i++)
        out[(size_t)(n0 + ty + 8 * i) * DIM + k0 + tx] = __float2half_rn(t[tx][ty + 8 * i]);
}

// ---------------------------------------------------------------------------
// Single-purpose transpose (V -> V^T half); in[K,N] fp32 -> out[N,K] half
// ---------------------------------------------------------------------------
__global__ void transpose_cvt_h_kernel(const float* __restrict__ in,
                                       __half* __restrict__ out, int K, int N)
{
    __shared__ float t[32][33];
    int k0 = blockIdx.y * 32, n0 = blockIdx.x * 32;
    int tx = threadIdx.x, ty = threadIdx.y;
#pragma unroll
    for (int i = 0; i < 4; i++)
        t[ty + 8 * i][tx] = in[(size_t)(k0 + ty + 8 * i) * N + n0 + tx];
    __syncthreads();
#pragma unroll
    for (int i = 0; i < 4; i++)
        out[(size_t)(n0 + ty + 8 * i) * K + k0 + tx] = __float2half_rn(t[tx][ty + 8 * i]);
}

// ---------------------------------------------------------------------------
// GEMM core constants (shared by proj + wo kernels)
// ---------------------------------------------------------------------------
#define HSTR 72                       // halfs per smem row (144 B)
#define HSTRB 144
#define HTILE (128 * HSTR)
#define HSTG (2 * HTILE)
#define NSTG 3
#define GEMM_SMEM (NSTG * HSTG * 2)   // 110592 B -> 2 CTAs/SM

// Mainloop macro-free shared implementation via inline function
struct GemmCore {
    uint32_t sm_u32;
    int tid, lane, warp, g, t4, wm, wn, lm, rr, lrow, lchk;
    uint32_t aoff, boff;
    __device__ __forceinline__ void init(const void* smem) {
        sm_u32 = (uint32_t)__cvta_generic_to_shared(smem);
        tid = threadIdx.x; lane = tid & 31; warp = tid >> 5;
        g = lane >> 2; t4 = lane & 3;
        wm = warp >> 1; wn = warp & 1;
        lm = lane >> 3; rr = lane & 7;
        aoff = (uint32_t)((wm * 32 + (lm & 1) * 8 + rr) * HSTRB + (lm >> 1) * 16);
        boff = (uint32_t)((wn * 64 + (lm >> 1) * 8 + rr) * HSTRB + (lm & 1) * 16);
        lrow = tid >> 3; lchk = tid & 7;
    }
};

__device__ __forceinline__ void gemm_mainloop(
    GemmCore& c, __half* smh, const __half* __restrict__ A,
    const __half* __restrict__ Bt, int bm, int bn, int lda, int ldb,
    int ktiles, float acc[2][8][4])
{
#pragma unroll
    for (int mi = 0; mi < 2; mi++)
#pragma unroll
        for (int ni = 0; ni < 8; ni++)
#pragma unroll
            for (int e = 0; e < 4; e++) acc[mi][ni][e] = 0.f;

    auto issue = [&](int stg, int t) {
        if (t < ktiles) {
            __half* As = smh + stg * HSTG;
            __half* Bs = As + HTILE;
            const int kc = t * 64 + c.lchk * 8;
#pragma unroll
            for (int p = 0; p < 4; p++) {
                int row = c.lrow + p * 32;
                cp_async16(&As[row * HSTR + c.lchk * 8],
                           &A[(size_t)(bm + row) * lda + kc]);
                cp_async16(&Bs[row * HSTR + c.lchk * 8],
                           &Bt[(size_t)(bn + row) * ldb + kc]);
            }
        }
        cp_commit();
    };

    issue(0, 0);
    issue(1, 1);

    for (int t = 0; t < ktiles; t++) {
        cp_wait<1>();
        __syncthreads();
        issue((t + 2) % NSTG, t + 2);

        const uint32_t aBase = c.sm_u32 + (uint32_t)((t % NSTG) * HSTG * 2) + c.aoff;
        const uint32_t bBase = aBase - c.aoff + (uint32_t)(HTILE * 2) + c.boff;

#pragma unroll
        for (int ks = 0; ks < 4; ks++) {
            uint32_t a[2][4], b[4][4];
#pragma unroll
            for (int mi = 0; mi < 2; mi++)
                ldsm_x4(a[mi], aBase + mi * 16 * HSTRB + ks * 32);
#pragma unroll
            for (int p = 0; p < 4; p++)
                ldsm_x4(b[p], bBase + p * 16 * HSTRB + ks * 32);
#pragma unroll
            for (int mi = 0; mi < 2; mi++)
#pragma unroll
                for (int ni = 0; ni < 8; ni++)
                    mma_f16(acc[mi][ni], a[mi], &b[ni >> 1][(ni & 1) * 2], acc[mi][ni]);
        }
    }
}

// ---------------------------------------------------------------------------
// Merged projection GEMM: ONE launch covers wq (1024 tiles), wk (256), wv (256).
// Q/K epilogues apply RoPE on fp32 accumulators and emit half directly
// (bit-identical to GEMM->fp32->rope->half). V epilogue emits fp32 for V^T.
// ---------------------------------------------------------------------------
__global__ __launch_bounds__(256, 2) void proj_gemm_kernel(
    const __half* __restrict__ xh,
    const __half* __restrict__ wqh, const __half* __restrict__ wkh,
    const __half* __restrict__ wvh,
    __half* __restrict__ qh, __half* __restrict__ kh, float* __restrict__ v,
    const float* __restrict__ fc, const float* __restrict__ fs)
{
    extern __shared__ __half smh[];
    GemmCore c; c.init(smh);

    const int bid = blockIdx.x;
    int mode, bx, by;
    const __half* Bt;
    if (bid < 1024)      { mode = 0; by = bid >> 5; bx = bid & 31; Bt = wqh; }
    else if (bid < 1280) { int t = bid - 1024; mode = 1; by = t >> 3; bx = t & 7; Bt = wkh; }
    else                 { int t = bid - 1280; mode = 2; by = t >> 3; bx = t & 7; Bt = wvh; }

    const int bm = by * 128, bn = bx * 128;
    float acc[2][8][4];
    gemm_mainloop(c, smh, xh, Bt, bm, bn, DIM, DIM, DIM / 64, acc);

    if (mode == 2) {
        // V: plain fp32 store
#pragma unroll
        for (int mi = 0; mi < 2; mi++)
#pragma unroll
            for (int ni = 0; ni < 8; ni++) {
                int r0 = bm + c.wm * 32 + mi * 16 + c.g;
                int cc = bn + c.wn * 64 + ni * 8 + c.t4 * 2;
                *reinterpret_cast<float2*>(&v[(size_t)r0 * KVDIM + cc]) =
                    make_float2(acc[mi][ni][0], acc[mi][ni][1]);
                *reinterpret_cast<float2*>(&v[(size_t)(r0 + 8) * KVDIM + cc]) =
                    make_float2(acc[mi][ni][2], acc[mi][ni][3]);
            }
    } else {
        // Q/K: fused RoPE on the (even, odd) pair each thread owns, emit half2
        __half* out = mode ? kh : qh;
        const int ldc = mode ? KVDIM : DIM;
#pragma unroll
        for (int mi = 0; mi < 2; mi++)
#pragma unroll
            for (int ni = 0; ni < 8; ni++) {
                int r0 = bm + c.wm * 32 + mi * 16 + c.g;
                int cc = bn + c.wn * 64 + ni * 8 + c.t4 * 2;
                int fi = (cc & (HD - 1)) >> 1;
                int s0 = r0 & (SEQLEN - 1), s1 = (r0 + 8) & (SEQLEN - 1);
                float c0 = fc[s0 * 64 + fi], n0 = fs[s0 * 64 + fi];
                float c1 = fc[s1 * 64 + fi], n1 = fs[s1 * 64 + fi];
                float e0 = acc[mi][ni][0], o0 = acc[mi][ni][1];
                float e1 = acc[mi][ni][2], o1 = acc[mi][ni][3];
                *reinterpret_cast<__half2*>(&out[(size_t)r0 * ldc + cc]) =
                    __floats2half2_rn(e0 * c0 - o0 * n0, e0 * n0 + o0 * c0);
                *reinterpret_cast<__half2*>(&out[(size_t)(r0 + 8) * ldc + cc]) =
                    __floats2half2_rn(e1 * c1 - o1 * n1, e1 * n1 + o1 * c1);
            }
    }
}

// ---------------------------------------------------------------------------
// Output-projection GEMM (half A/B, fp32 C)
// ---------------------------------------------------------------------------
__global__ __launch_bounds__(256, 2) void gemm_f16_kernel(
    const __half* __restrict__ A, const __half* __restrict__ Bt,
    float* __restrict__ C, int M, int N, int K, int lda, int ldb, int ldc)
{
    extern __shared__ __half smh[];
    GemmCore c; c.init(smh);
    const int bm = blockIdx.y * 128, bn = blockIdx.x * 128;
    float acc[2][8][4];
    gemm_mainloop(c, smh, A, Bt, bm, bn, lda, ldb, K / 64, acc);
#pragma unroll
    for (int mi = 0; mi < 2; mi++)
#pragma unroll
        for (int ni = 0; ni < 8; ni++) {
            int r0 = bm + c.wm * 32 + mi * 16 + c.g;
            int cc = bn + c.wn * 64 + ni * 8 + c.t4 * 2;
            *reinterpret_cast<float2*>(&C[(size_t)r0 * ldc + cc]) =
                make_float2(acc[mi][ni][0], acc[mi][ni][1]);
            *reinterpret_cast<float2*>(&C[(size_t)(r0 + 8) * ldc + cc]) =
                make_float2(acc[mi][ni][2], acc[mi][ni][3]);
        }
}

// ---------------------------------------------------------------------------
// Flash attention v4 (causal, GQA), ALL-FP16 operands, fp32 accum/softmax.
// 128 q-rows/CTA, 256 threads (8 warps), Q in regs, 64-key j-tiles,
// full-ldmatrix, LPT grid ordering. (Unchanged from R11.)
// ---------------------------------------------------------------------------
#define KSTRH 136
#define VSTRH 72
#define KT_H (64 * KSTRH)
#define VT_H (128 * VSTRH)
#define PQ_H (128 * KSTRH)
#define ATTN_SMEM ((2 * KT_H + 2 * VT_H + PQ_H) * 2)   // 106496 B

__global__ __launch_bounds__(256) void attn_kernel(
    const __half* __restrict__ Qh, const __half* __restrict__ Kh,
    const __half* __restrict__ Vth, __half* __restrict__ ctxh)
{
    extern __shared__ __half smh[];
    __half* Ksb[2] = { smh, smh + KT_H };
    __half* Vsb[2] = { smh + 2 * KT_H, smh + 2 * KT_H + VT_H };
    __half* Ps     = smh + 2 * KT_H + 2 * VT_H;
    const uint32_t sm_u32 = (uint32_t)__cvta_generic_to_shared(smh);
    const uint32_t ks_u[2] = { sm_u32, sm_u32 + KT_H * 2 };
    const uint32_t vs_u[2] = { sm_u32 + 2 * KT_H * 2, sm_u32 + (2 * KT_H + VT_H) * 2 };
    const uint32_t ps_u = sm_u32 + (2 * KT_H + 2 * VT_H) * 2;

    const int hb = blockIdx.x;
    const int h = hb & (NHEADS - 1), b = hb >> 5;
    const int qt = (gridDim.y - 1) - blockIdx.y;          // LPT
    const int hkv = h >> 2;
    const int tid = threadIdx.x, lane = tid & 31, warp = tid >> 5;
    const int g = lane >> 2, t4 = lane & 3;
    const int lm = lane >> 3, rr = lane & 7;

    const uint32_t qoff = (uint32_t)((warp * 16 + (lm & 1) * 8 + rr) * (KSTRH * 2) + (lm >> 1) * 16);
    const uint32_t poff = (uint32_t)((warp * 16 + (lm & 1) * 8 + rr) * (VSTRH * 2) + (lm >> 1) * 16);
    const uint32_t koff = (uint32_t)(((lm >> 1) * 8 + rr) * (KSTRH * 2) + (lm & 1) * 16);
    const uint32_t voff = (uint32_t)(((lm >> 1) * 8 + rr) * (VSTRH * 2) + (lm & 1) * 16);

    {
        const int r0 = tid >> 4, c8 = (tid & 15) * 8;
#pragma unroll
        for (int p = 0; p < 8; p++) {
            int r = r0 + p * 16;
            int gr = b * SEQLEN + qt * 128 + r;
            *reinterpret_cast<uint4*>(&Ps[r * KSTRH + c8]) =
                *reinterpret_cast<const uint4*>(&Qh[(size_t)gr * DIM + h * HD + c8]);
        }
    }
    __syncthreads();
    uint32_t qf[8][4];
#pragma unroll
    for (int ks = 0; ks < 8; ks++)
        ldsm_x4(qf[ks], ps_u + qoff + ks * 32);

    auto issue_kv = [&](int buf, int j) {
        __half* Ks = Ksb[buf];
        __half* Vs = Vsb[buf];
        const int kr0 = tid >> 4, kc8 = (tid & 15) * 8;
#pragma unroll
        for (int p = 0; p < 4; p++) {
            int r = kr0 + p * 16;
            int gr = b * SEQLEN + j * 64 + r;
            cp_async16(&Ks[r * KSTRH + kc8], &Kh[(size_t)gr * KVDIM + hkv * HD + kc8]);
        }
        const int vrow = tid >> 1, vc0 = (tid & 1) * 32;
        const __half* vsrc = &Vth[(size_t)(hkv * HD + vrow) * MROWS + b * SEQLEN + j * 64 + vc0];
#pragma unroll
        for (int cc = 0; cc < 4; cc++)
            cp_async16(&Vs[vrow * VSTRH + vc0 + cc * 8], vsrc + cc * 8);
        cp_commit();
    };

    float m_s[2] = {-1e30f, -1e30f};
    float l_s[2] = {0.f, 0.f};
    float o[16][4];
#pragma unroll
    for (int di = 0; di < 16; di++)
#pragma unroll
        for (int e = 0; e < 4; e++) o[di][e] = 0.f;

    const float scale = 0.08838834764831845f;
    const int rowbase = qt * 128 + warp * 16;
    const int jmax = 2 * qt + 1;

    issue_kv(0, 0);

    for (int j = 0; j <= jmax; j++) {
        cp_wait<0>();
        __syncthreads();
        if (j + 1 <= jmax) issue_kv((j + 1) & 1, j + 1);

        const bool skip = (j * 64) > rowbase + 15;
        if (!skip) {
            const uint32_t kb = ks_u[j & 1] + koff;
            const uint32_t vb = vs_u[j & 1] + voff;

            float s[8][4];
#pragma unroll
            for (int ni = 0; ni < 8; ni++)
#pragma unroll
                for (int e = 0; e < 4; e++) s[ni][e] = 0.f;

#pragma unroll
            for (int ks = 0; ks < 8; ks++) {
                uint32_t kf[4][4];
#pragma unroll
                for (int p = 0; p < 4; p++)
                    ldsm_x4(kf[p], kb + p * 16 * (KSTRH * 2) + ks * 32);
#pragma unroll
                for (int ni = 0; ni < 8; ni++)
                    mma_f16(s[ni], qf[ks], &kf[ni >> 1][(ni & 1) * 2], s[ni]);
            }

#pragma unroll
            for (int ni = 0; ni < 8; ni++)
#pragma unroll
                for (int e = 0; e < 4; e++) s[ni][e] *= scale;
            if (j * 64 + 63 > rowbase) {
#pragma unroll
                for (int ni = 0; ni < 8; ni++)
#pragma unroll
                    for (int e = 0; e < 4; e++) {
                        int qr = rowbase + g + (e >> 1) * 8;
                        int kc = j * 64 + ni * 8 + t4 * 2 + (e & 1);
                        if (kc > qr) s[ni][e] = -1e30f;
                    }
            }

#pragma unroll
            for (int rw = 0; rw < 2; rw++) {
                float mx = -1e30f;
#pragma unroll
                for (int ni = 0; ni < 8; ni++)
                    mx = fmaxf(mx, fmaxf(s[ni][rw * 2], s[ni][rw * 2 + 1]));
                mx = fmaxf(mx, __shfl_xor_sync(0xffffffffu, mx, 1));
                mx = fmaxf(mx, __shfl_xor_sync(0xffffffffu, mx, 2));
                float nm = fmaxf(m_s[rw], mx);
                float alpha = __expf(m_s[rw] - nm);
                m_s[rw] = nm;
                float rsum = 0.f;
#pragma unroll
                for (int ni = 0; ni < 8; ni++) {
#pragma unroll
                    for (int cc = 0; cc < 2; cc++) {
                        float pv = __expf(s[ni][rw * 2 + cc] - nm);
                        s[ni][rw * 2 + cc] = pv;
                        rsum += pv;
                    }
                }
                rsum += __shfl_xor_sync(0xffffffffu, rsum, 1);
                rsum += __shfl_xor_sync(0xffffffffu, rsum, 2);
                l_s[rw] = l_s[rw] * alpha + rsum;
#pragma unroll
                for (int di = 0; di < 16; di++) {
                    o[di][rw * 2] *= alpha;
                    o[di][rw * 2 + 1] *= alpha;
                }
            }

            __syncwarp();
#pragma unroll
            for (int ni = 0; ni < 8; ni++)
#pragma unroll
                for (int rw = 0; rw < 2; rw++) {
                    int pr = warp * 16 + g + rw * 8;
                    int pc = ni * 8 + t4 * 2;
                    *reinterpret_cast<__half2*>(&Ps[pr * VSTRH + pc]) =
                        __floats2half2_rn(s[ni][rw * 2], s[ni][rw * 2 + 1]);
                }
            __syncwarp();

#pragma unroll
            for (int ks = 0; ks < 4; ks++) {
                uint32_t a[4], vf[8][4];
                ldsm_x4(a, ps_u + poff + ks * 32);
#pragma unroll
                for (int p = 0; p < 8; p++)
                    ldsm_x4(vf[p], vb + p * 16 * (VSTRH * 2) + ks * 32);
#pragma unroll
                for (int di = 0; di < 16; di++)
                    mma_f16(o[di], a, &vf[di >> 1][(di & 1) * 2], o[di]);
            }
        }
    }

#pragma unroll
    for (int rw = 0; rw < 2; rw++) {
        float inv = 1.0f / l_s[rw];
        int gr = b * SEQLEN + rowbase + g + rw * 8;
#pragma unroll
        for (int di = 0; di < 16; di++) {
            *reinterpret_cast<__half2*>(
                &ctxh[(size_t)gr * DIM + h * HD + di * 8 + t4 * 2]) =
                __floats2half2_rn(o[di][rw * 2] * inv, o[di][rw * 2 + 1] * inv);
        }
    }
}

// ---------------------------------------------------------------------------
// launch
// ---------------------------------------------------------------------------
extern "C" void kernel_launch(void* const* d_in, const int* in_sizes, int n_in,
                              void* d_out, int out_size)
{
    const float* x  = (const float*)d_in[0];
    const float* wq = (const float*)d_in[1];
    const float* wk = (const float*)d_in[2];
    const float* wv = (const float*)d_in[3];
    const float* wo = (const float*)d_in[4];
    const float* fc = (const float*)d_in[5];
    const float* fs = (const float*)d_in[6];
    // d_in[7] = mask (causal, applied analytically), d_in[8] = start_pos (0)
    float* out = (float*)d_out;

    float *v;
    __half *qh, *kh, *vth, *ctxh, *xh, *wqh, *wkh, *wvh, *woh;
    cudaGetSymbolAddress((void**)&v,    g_v);
    cudaGetSymbolAddress((void**)&qh,   g_qh);
    cudaGetSymbolAddress((void**)&kh,   g_kh);
    cudaGetSymbolAddress((void**)&vth,  g_vth);
    cudaGetSymbolAddress((void**)&ctxh, g_ctxh);
    cudaGetSymbolAddress((void**)&xh,   g_xh);
    cudaGetSymbolAddress((void**)&wqh,  g_wqh);
    cudaGetSymbolAddress((void**)&wkh,  g_wkh);
    cudaGetSymbolAddress((void**)&wvh,  g_wvh);
    cudaGetSymbolAddress((void**)&woh,  g_woh);

    cudaFuncSetAttribute(proj_gemm_kernel,
                         cudaFuncAttributeMaxDynamicSharedMemorySize, GEMM_SMEM);
    cudaFuncSetAttribute(gemm_f16_kernel,
                         cudaFuncAttributeMaxDynamicSharedMemorySize, GEMM_SMEM);
    cudaFuncSetAttribute(attn_kernel,
                         cudaFuncAttributeMaxDynamicSharedMemorySize, ATTN_SMEM);

    // x -> half; all 4 weight transposes in ONE launch
    int n4_big = MROWS * DIM / 4;
    cvt_h_kernel<<<(n4_big + 255) / 256, 256>>>((const float4*)x, (uint2*)xh, n4_big);
    transpose_all_kernel<<<dim3(DIM / 32, DIM / 32, 4), dim3(32, 8)>>>(
        wq, wk, wv, wo, wqh, wkh, wvh, woh);

    // ALL projections in ONE 1536-CTA launch; RoPE fused into Q/K epilogues
    proj_gemm_kernel<<<1536, 256, GEMM_SMEM>>>(xh, wqh, wkh, wvh, qh, kh, v, fc, fs);

    // V^T (half) for ldmatrix B-fragments in attention
    transpose_cvt_h_kernel<<<dim3(KVDIM / 32, MROWS / 32), dim3(32, 8)>>>(v, vth, MROWS, KVDIM);

    // Causal flash attention (half in, half out), LPT-ordered
    attn_kernel<<<dim3(NHEADS * BSZ, SEQLEN / 128), 256, ATTN_SMEM>>>(qh, kh, vth, ctxh);

    // Output projection (half ctx @ half wo -> fp32 out)
    gemm_f16_kernel<<<dim3(DIM / 128, MROWS / 128), 256, GEMM_SMEM>>>(
        ctxh, woh, out, MROWS, DIM, DIM, DIM, DIM, DIM);
}